// round 2
// baseline (speedup 1.0000x reference)
#include <cuda_runtime.h>
#include <cuda_bf16.h>
#include <math.h>

// ---------------------------------------------------------------------------
// Problem constants
// ---------------------------------------------------------------------------
#define BATCH 8
#define HH    64
#define WW    64
#define CC    256
#define GG    8
#define GCH   32            // CC / GG
#define K2    9
#define PADB  1
#define HP    66            // HH + 2*PADB
#define WP    66
#define NPIX  (BATCH*HH*WW) // 32768

// ---------------------------------------------------------------------------
// Scratch (device globals; no allocation allowed). Referenced directly from
// device code so kernel_launch contains ONLY kernel launches.
// ---------------------------------------------------------------------------
__device__ float g_xpad[BATCH * HP * WP * CC];   // padded x_proj (~35.7 MB)
__device__ float g_x1  [NPIX * CC];              // dwconv+LN+GELU
__device__ float g_off [NPIX * 144];             // offsets (g,k,2)
__device__ float g_mask[NPIX * 72];              // mask logits -> softmax in place
__device__ float g_samp[NPIX * CC];              // deformable gather output

// ---------------------------------------------------------------------------
// Zero the padded buffer (ring must be zero; interior is overwritten by GEMM)
// ---------------------------------------------------------------------------
__global__ void zero_xpad_kernel() {
    int i = blockIdx.x * blockDim.x + threadIdx.x;
    const int total4 = (BATCH * HP * WP * CC) / 4;
    if (i < total4) ((float4*)g_xpad)[i] = make_float4(0.f, 0.f, 0.f, 0.f);
}

// ---------------------------------------------------------------------------
// SIMT fp32 GEMM: C[M,N] = A[M,256] @ B[256,N] + bias
// BM=128, BN=64, BK=16, 256 threads, 8x4 per thread. M == NPIX always.
// SRC: 0 = external A pointer, 1 = g_x1, 2 = g_samp
// DST: 0 = external C pointer, 1 = g_xpad (padded layout), 2 = g_off, 3 = g_mask
// ---------------------------------------------------------------------------
#define GBM 128
#define GBN 64
#define GBK 16

template<int SRC, int DST>
__global__ __launch_bounds__(256)
void sgemm_kernel(const float* __restrict__ Aext,
                  const float* __restrict__ B,
                  const float* __restrict__ bias,
                  float* __restrict__ Cext,
                  int N) {
    const float* __restrict__ A =
        (SRC == 0) ? Aext : (SRC == 1) ? (const float*)g_x1 : (const float*)g_samp;
    float* __restrict__ C =
        (DST == 0) ? Cext : (DST == 2) ? (float*)g_off :
        (DST == 3) ? (float*)g_mask : (float*)g_xpad;

    __shared__ float As[GBK][GBM];
    __shared__ float Bs[GBK][GBN];
    const int K = CC;

    int tid  = threadIdx.x;
    int brow = blockIdx.y * GBM;
    int bcol = blockIdx.x * GBN;
    int tx = tid & 15;
    int ty = tid >> 4;

    float acc[8][4];
#pragma unroll
    for (int i = 0; i < 8; i++)
#pragma unroll
        for (int j = 0; j < 4; j++) acc[i][j] = 0.f;

    // A: 128x16 floats = 512 float4, 2 per thread
    int ar0 = tid >> 2,         ac0 = (tid & 3) * 4;
    int ar1 = (tid + 256) >> 2, ac1 = ac0;
    // B: 16x64 floats = 256 float4, 1 per thread
    int brl = tid >> 4;
    int bcl = (tid & 15) * 4;

    for (int k0 = 0; k0 < K; k0 += GBK) {
        float4 a0 = *(const float4*)(A + (size_t)(brow + ar0) * K + k0 + ac0);
        float4 a1 = *(const float4*)(A + (size_t)(brow + ar1) * K + k0 + ac1);
        As[ac0 + 0][ar0] = a0.x; As[ac0 + 1][ar0] = a0.y;
        As[ac0 + 2][ar0] = a0.z; As[ac0 + 3][ar0] = a0.w;
        As[ac1 + 0][ar1] = a1.x; As[ac1 + 1][ar1] = a1.y;
        As[ac1 + 2][ar1] = a1.z; As[ac1 + 3][ar1] = a1.w;

        int gc = bcol + bcl;
        if (gc + 3 < N) {
            float4 bv = *(const float4*)(B + (size_t)(k0 + brl) * N + gc);
            *(float4*)&Bs[brl][bcl] = bv;
        } else {
#pragma unroll
            for (int j = 0; j < 4; j++)
                Bs[brl][bcl + j] = (gc + j < N) ? B[(size_t)(k0 + brl) * N + gc + j] : 0.f;
        }
        __syncthreads();

#pragma unroll
        for (int kk = 0; kk < GBK; kk++) {
            float4 a0v = *(const float4*)&As[kk][ty * 8];
            float4 a1v = *(const float4*)&As[kk][ty * 8 + 4];
            float4 bv  = *(const float4*)&Bs[kk][tx * 4];
            float ar[8] = {a0v.x, a0v.y, a0v.z, a0v.w, a1v.x, a1v.y, a1v.z, a1v.w};
            float br[4] = {bv.x, bv.y, bv.z, bv.w};
#pragma unroll
            for (int i = 0; i < 8; i++)
#pragma unroll
                for (int j = 0; j < 4; j++)
                    acc[i][j] += ar[i] * br[j];
        }
        __syncthreads();
    }

#pragma unroll
    for (int i = 0; i < 8; i++) {
        int row = brow + ty * 8 + i;
        size_t obase;
        if (DST == 1) {
            int b = row >> 12, h = (row >> 6) & 63, w = row & 63;
            obase = ((size_t)(b * HP + h + 1) * WP + (w + 1)) * CC;
        } else {
            obase = (size_t)row * N;
        }
#pragma unroll
        for (int j = 0; j < 4; j++) {
            int c = bcol + tx * 4 + j;
            if (c < N) C[obase + c] = acc[i][j] + bias[c];
        }
    }
}

// ---------------------------------------------------------------------------
// Depthwise 3x3 conv (SAME, zero pad) + LayerNorm + exact GELU
// One block per pixel, one thread per channel.
// ---------------------------------------------------------------------------
__global__ __launch_bounds__(256)
void dwlngelu_kernel(const float* __restrict__ in,
                     const float* __restrict__ dwk,
                     const float* __restrict__ dwb,
                     const float* __restrict__ gamma,
                     const float* __restrict__ beta) {
    int p = blockIdx.x;
    int c = threadIdx.x;
    int b = p >> 12, h = (p >> 6) & 63, w = p & 63;

    float s = dwb[c];
#pragma unroll
    for (int ky = 0; ky < 3; ky++) {
        int hh = h + ky - 1;
        if (hh < 0 || hh >= HH) continue;
#pragma unroll
        for (int kx = 0; kx < 3; kx++) {
            int ww = w + kx - 1;
            if (ww < 0 || ww >= WW) continue;
            s += in[((size_t)(b * HH + hh) * WW + ww) * CC + c] *
                 dwk[(ky * 3 + kx) * CC + c];
        }
    }

    __shared__ float rs[256];
    __shared__ float rs2[256];
    rs[c]  = s;
    rs2[c] = s * s;
    __syncthreads();
#pragma unroll
    for (int off = 128; off > 0; off >>= 1) {
        if (c < off) { rs[c] += rs[c + off]; rs2[c] += rs2[c + off]; }
        __syncthreads();
    }
    float mu  = rs[0] * (1.0f / 256.0f);
    float var = rs2[0] * (1.0f / 256.0f) - mu * mu;
    float y = (s - mu) * rsqrtf(var + 1e-6f) * gamma[c] + beta[c];
    // exact gelu: 0.5*y*(1+erf(y/sqrt(2)))
    g_x1[(size_t)p * CC + c] = 0.5f * y * (1.0f + erff(y * 0.70710678118654752f));
}

// ---------------------------------------------------------------------------
// Softmax over the 9 kernel taps per (pixel, group), in place on g_mask.
// ---------------------------------------------------------------------------
__global__ void mask_softmax_kernel() {
    int i = blockIdx.x * blockDim.x + threadIdx.x;
    if (i >= NPIX * GG) return;
    int p = i >> 3, g = i & 7;
    float* m = g_mask + (size_t)p * 72 + g * 9;
    float v[K2], mx = -1e30f;
#pragma unroll
    for (int k = 0; k < K2; k++) { v[k] = m[k]; mx = fmaxf(mx, v[k]); }
    float den = 0.f;
#pragma unroll
    for (int k = 0; k < K2; k++) { v[k] = __expf(v[k] - mx); den += v[k]; }
    float inv = 1.0f / den;
#pragma unroll
    for (int k = 0; k < K2; k++) m[k] = v[k] * inv;
}

// ---------------------------------------------------------------------------
// Deformable bilinear gather: one block per pixel, one warp per group,
// one lane per group channel. Samples from padded g_xpad (zeros outside).
// ---------------------------------------------------------------------------
__global__ __launch_bounds__(256)
void deform_sample_kernel() {
    int p    = blockIdx.x;
    int g    = threadIdx.x >> 5;
    int lane = threadIdx.x & 31;
    int b = p >> 12, h = (p >> 6) & 63, w = p & 63;

    const float* offp = g_off  + (size_t)p * 144 + g * 18;
    const float* mp   = g_mask + (size_t)p * 72  + g * 9;
    const float* base = g_xpad + (size_t)b * HP * WP * CC + g * GCH + lane;

    float acc = 0.f;
#pragma unroll
    for (int k = 0; k < K2; k++) {
        float ox = offp[k * 2 + 0];
        float oy = offp[k * 2 + 1];
        float px = (float)(PADB + w) + (float)(k % 3 - 1) + ox;
        float py = (float)(PADB + h) + (float)(k / 3 - 1) + oy;
        float mk = mp[k];

        float x0f = floorf(px), y0f = floorf(py);
        int x0 = (int)x0f, y0 = (int)y0f;
        float wx = px - x0f, wy = py - y0f;

        float v00 = 0.f, v01 = 0.f, v10 = 0.f, v11 = 0.f;
        bool xv0 = (x0 >= 0) & (x0 < WP);
        bool xv1 = (x0 + 1 >= 0) & (x0 + 1 < WP);
        bool yv0 = (y0 >= 0) & (y0 < HP);
        bool yv1 = (y0 + 1 >= 0) & (y0 + 1 < HP);
        if (yv0) {
            const float* r0 = base + (size_t)y0 * WP * CC;
            if (xv0) v00 = r0[(size_t)x0 * CC];
            if (xv1) v01 = r0[(size_t)(x0 + 1) * CC];
        }
        if (yv1) {
            const float* r1 = base + (size_t)(y0 + 1) * WP * CC;
            if (xv0) v10 = r1[(size_t)x0 * CC];
            if (xv1) v11 = r1[(size_t)(x0 + 1) * CC];
        }
        float sx0 = v00 * (1.f - wx) + v01 * wx;
        float sx1 = v10 * (1.f - wx) + v11 * wx;
        acc += mk * (sx0 * (1.f - wy) + sx1 * wy);
    }
    g_samp[(size_t)p * CC + g * GCH + lane] = acc;
}

// ---------------------------------------------------------------------------
// Launch: kernel launches ONLY (graph-capture safe, no runtime API calls)
// ---------------------------------------------------------------------------
extern "C" void kernel_launch(void* const* d_in, const int* in_sizes, int n_in,
                              void* d_out, int out_size) {
    const float* inputs   = (const float*)d_in[0];
    const float* w_in     = (const float*)d_in[1];
    const float* b_in     = (const float*)d_in[2];
    const float* dw_k     = (const float*)d_in[3];
    const float* dw_b     = (const float*)d_in[4];
    const float* ln_gamma = (const float*)d_in[5];
    const float* ln_beta  = (const float*)d_in[6];
    const float* w_off    = (const float*)d_in[7];
    const float* b_off    = (const float*)d_in[8];
    const float* w_mask   = (const float*)d_in[9];
    const float* b_mask   = (const float*)d_in[10];
    const float* w_out    = (const float*)d_in[11];
    const float* b_out    = (const float*)d_in[12];
    float* out = (float*)d_out;

    // 1) zero padded buffer
    {
        int total4 = (BATCH * HP * WP * CC) / 4;
        zero_xpad_kernel<<<(total4 + 255) / 256, 256>>>();
    }
    // 2) x_proj GEMM -> padded layout (SRC=ext inputs, DST=g_xpad)
    {
        dim3 grid((CC + GBN - 1) / GBN, NPIX / GBM);
        sgemm_kernel<0, 1><<<grid, 256>>>(inputs, w_in, b_in, nullptr, CC);
    }
    // 3) depthwise conv + LN + GELU -> g_x1
    dwlngelu_kernel<<<NPIX, 256>>>(inputs, dw_k, dw_b, ln_gamma, ln_beta);
    // 4) offset GEMM (N=144): g_x1 -> g_off
    {
        dim3 grid((144 + GBN - 1) / GBN, NPIX / GBM);
        sgemm_kernel<1, 2><<<grid, 256>>>(nullptr, w_off, b_off, nullptr, 144);
    }
    // 5) mask GEMM (N=72): g_x1 -> g_mask, then softmax in place
    {
        dim3 grid((72 + GBN - 1) / GBN, NPIX / GBM);
        sgemm_kernel<1, 3><<<grid, 256>>>(nullptr, w_mask, b_mask, nullptr, 72);
        mask_softmax_kernel<<<(NPIX * GG + 255) / 256, 256>>>();
    }
    // 6) deformable bilinear gather -> g_samp
    deform_sample_kernel<<<NPIX, 256>>>();
    // 7) output GEMM: g_samp -> out
    {
        dim3 grid((CC + GBN - 1) / GBN, NPIX / GBM);
        sgemm_kernel<2, 0><<<grid, 256>>>(nullptr, w_out, b_out, out, CC);
    }
    (void)in_sizes; (void)n_in; (void)out_size;
}

// round 3
// speedup vs baseline: 1.1174x; 1.1174x over previous
#include <cuda_runtime.h>
#include <cuda_bf16.h>
#include <math.h>
#include <stdint.h>

// ---------------------------------------------------------------------------
// Problem constants
// ---------------------------------------------------------------------------
#define BATCH 8
#define HH    64
#define WW    64
#define CC    256
#define GG    8
#define GCH   32
#define K2    9
#define PADB  1
#define HP    66
#define WP    66
#define NPIX  (BATCH*HH*WW) // 32768

// ---------------------------------------------------------------------------
// Scratch (device globals)
// ---------------------------------------------------------------------------
__device__ float g_xpad[BATCH * HP * WP * CC];
__device__ float g_x1  [NPIX * CC];
__device__ float g_off [NPIX * 144];
__device__ float g_mask[NPIX * 72];
__device__ float g_samp[NPIX * CC];

// ---------------------------------------------------------------------------
// Zero only the 1-pixel ring of the padded buffer (interior overwritten).
// 8 * 260 ring pixels * 256 ch = 2080*256 floats = 133120 float4
// ---------------------------------------------------------------------------
__global__ void zero_ring_kernel() {
    int idx = blockIdx.x * blockDim.x + threadIdx.x;
    const int total = BATCH * 260 * 64;
    if (idx >= total) return;
    int p  = idx >> 6;
    int c4 = idx & 63;
    int b = p / 260;
    int r = p % 260;
    int h, w;
    if (r < 66)        { h = 0;        w = r; }
    else if (r < 132)  { h = 65;       w = r - 66; }
    else if (r < 196)  { h = r - 131;  w = 0; }
    else               { h = r - 195;  w = 65; }
    size_t a = (((size_t)(b * HP + h) * WP + w) * CC) + c4 * 4;
    *(float4*)(g_xpad + a) = make_float4(0.f, 0.f, 0.f, 0.f);
}

// ---------------------------------------------------------------------------
// TF32 helpers
// ---------------------------------------------------------------------------
__device__ __forceinline__ unsigned tf32_bits(float x) {
    unsigned u; asm("cvt.rna.tf32.f32 %0, %1;" : "=r"(u) : "f"(x)); return u;
}

#define MMA_TF32(d, a, b)                                                     \
    asm volatile("mma.sync.aligned.m16n8k8.row.col.f32.tf32.tf32.f32 "        \
        "{%0,%1,%2,%3}, {%4,%5,%6,%7}, {%8,%9}, {%0,%1,%2,%3};"               \
        : "+f"((d)[0]), "+f"((d)[1]), "+f"((d)[2]), "+f"((d)[3])              \
        : "r"((a)[0]), "r"((a)[1]), "r"((a)[2]), "r"((a)[3]),                 \
          "r"((b)[0]), "r"((b)[1]))

// ---------------------------------------------------------------------------
// Tensor-core TF32 GEMM: C[M,N] = A[M,256] @ B[256,N] + bias
// BM=128 BN=64 BK=16, 128 threads (4 warps, 2x2, warp tile 64x32).
// SPLIT: 3xTF32 (hi/lo) for ~fp32 accuracy.
// k-permuted smem: within each 8-col group, logical col l stored at
//   s = (l<4) ? 2l : 2(l-4)+1  -> fragment loads become float2 (LDS.64).
// SRC: 0 ext, 1 g_x1, 2 g_samp.  DST: 0 ext, 1 g_xpad(padded), 2 g_off, 3 g_mask
// ---------------------------------------------------------------------------
#define TBM 128
#define TBN 64
#define TPADK 24

template<bool SPLIT> struct SmemT;
template<> struct SmemT<true>  { float A[2][TBM][TPADK]; float Bm[2][TBN][TPADK]; };
template<> struct SmemT<false> { float A[1][TBM][TPADK]; float Bm[1][TBN][TPADK]; };

template<int SRC, int DST, bool SPLIT>
__global__ void sgemm_tc(const float* __restrict__ Aext,
                         const float* __restrict__ Bg,
                         const float* __restrict__ bias,
                         float* __restrict__ Cext,
                         int N) {
    const float* __restrict__ A =
        (SRC == 0) ? Aext : (SRC == 1) ? (const float*)g_x1 : (const float*)g_samp;
    float* __restrict__ C =
        (DST == 0) ? Cext : (DST == 2) ? (float*)g_off :
        (DST == 3) ? (float*)g_mask : (float*)g_xpad;

    __shared__ SmemT<SPLIT> sm;

    const int tid  = threadIdx.x;
    const int warp = tid >> 5;
    const int lane = tid & 31;
    const int wm = warp >> 1;        // 0..1
    const int wn = warp & 1;         // 0..1
    const int gq = lane >> 2;        // 0..7
    const int tq = lane & 3;         // 0..3
    const int brow = blockIdx.y * TBM;
    const int bcol = blockIdx.x * TBN;

    float d[4][4][4];
#pragma unroll
    for (int i = 0; i < 4; i++)
#pragma unroll
        for (int j = 0; j < 4; j++)
#pragma unroll
            for (int k = 0; k < 4; k++) d[i][j][k] = 0.f;

    // gmem prefetch registers
    float4 pa[4];
    float4 pb[2];

    const int arow = tid >> 2;            // 0..31
    const int aq   = tid & 3;             // col quarter
    const int bk   = tid >> 3;            // 0..15
    const int bnq  = tid & 7;

    // ---- gmem load helpers ----
    auto ldgA = [&](int k0) {
#pragma unroll
        for (int rr = 0; rr < 4; rr++) {
            int row = rr * 32 + arow;
            pa[rr] = *(const float4*)(A + (size_t)(brow + row) * CC + k0 + aq * 4);
        }
    };
    auto ldgB = [&](int k0) {
#pragma unroll
        for (int i = 0; i < 2; i++) {
            int nl = (bnq + i * 8) * 4;
            int gc = bcol + nl;
            if (gc < N)
                pb[i] = *(const float4*)(Bg + (size_t)(k0 + bk) * N + gc);
            else
                pb[i] = make_float4(0.f, 0.f, 0.f, 0.f);
        }
    };
    // ---- smem store helpers (k-permuted, tf32-rounded) ----
    auto stsA = [&]() {
        int cb = (aq >> 1) * 8 + (aq & 1);
#pragma unroll
        for (int rr = 0; rr < 4; rr++) {
            int row = rr * 32 + arow;
            float v[4] = {pa[rr].x, pa[rr].y, pa[rr].z, pa[rr].w};
#pragma unroll
            for (int j = 0; j < 4; j++) {
                unsigned hb = tf32_bits(v[j]);
                float hf = __uint_as_float(hb);
                sm.A[0][row][cb + 2 * j] = hf;
                if (SPLIT)
                    sm.A[1][row][cb + 2 * j] = __uint_as_float(tf32_bits(v[j] - hf));
            }
        }
    };
    auto stsB = [&]() {
        int c = bk & 7;
        int scol = (bk >> 3) * 8 + ((c < 4) ? 2 * c : 2 * c - 7);
#pragma unroll
        for (int i = 0; i < 2; i++) {
            int nb = (bnq + i * 8) * 4;
            float v[4] = {pb[i].x, pb[i].y, pb[i].z, pb[i].w};
#pragma unroll
            for (int j = 0; j < 4; j++) {
                unsigned hb = tf32_bits(v[j]);
                float hf = __uint_as_float(hb);
                sm.Bm[0][nb + j][scol] = hf;
                if (SPLIT)
                    sm.Bm[1][nb + j][scol] = __uint_as_float(tf32_bits(v[j] - hf));
            }
        }
    };
    // ---- compute: 2 k8-groups from the smem tile ----
    auto compute = [&]() {
#pragma unroll
        for (int kg = 0; kg < 2; kg++) {
            unsigned ah[4][4], bh[4][2];
            unsigned al[4][4], bl[4][2];
#pragma unroll
            for (int ms = 0; ms < 4; ms++) {
                int r = wm * 64 + ms * 16 + gq;
                float2 x = *(float2*)&sm.A[0][r][kg * 8 + 2 * tq];
                float2 y = *(float2*)&sm.A[0][r + 8][kg * 8 + 2 * tq];
                ah[ms][0] = __float_as_uint(x.x); ah[ms][1] = __float_as_uint(y.x);
                ah[ms][2] = __float_as_uint(x.y); ah[ms][3] = __float_as_uint(y.y);
                if (SPLIT) {
                    float2 xl = *(float2*)&sm.A[1][r][kg * 8 + 2 * tq];
                    float2 yl = *(float2*)&sm.A[1][r + 8][kg * 8 + 2 * tq];
                    al[ms][0] = __float_as_uint(xl.x); al[ms][1] = __float_as_uint(yl.x);
                    al[ms][2] = __float_as_uint(xl.y); al[ms][3] = __float_as_uint(yl.y);
                }
            }
#pragma unroll
            for (int ns = 0; ns < 4; ns++) {
                int n = wn * 32 + ns * 8 + gq;
                float2 z = *(float2*)&sm.Bm[0][n][kg * 8 + 2 * tq];
                bh[ns][0] = __float_as_uint(z.x); bh[ns][1] = __float_as_uint(z.y);
                if (SPLIT) {
                    float2 zl = *(float2*)&sm.Bm[1][n][kg * 8 + 2 * tq];
                    bl[ns][0] = __float_as_uint(zl.x); bl[ns][1] = __float_as_uint(zl.y);
                }
            }
#pragma unroll
            for (int ms = 0; ms < 4; ms++)
#pragma unroll
                for (int ns = 0; ns < 4; ns++) {
                    MMA_TF32(d[ms][ns], ah[ms], bh[ns]);
                    if (SPLIT) {
                        MMA_TF32(d[ms][ns], ah[ms], bl[ns]);
                        MMA_TF32(d[ms][ns], al[ms], bh[ns]);
                    }
                }
        }
    };

    // ---- pipeline ----
    ldgA(0); ldgB(0);
    stsA(); stsB();
    __syncthreads();
#pragma unroll 1
    for (int it = 0; it < 16; it++) {
        if (it < 15) { ldgA((it + 1) * 16); ldgB((it + 1) * 16); }
        compute();
        if (it < 15) {
            __syncthreads();
            stsA(); stsB();
            __syncthreads();
        }
    }

    // ---- epilogue ----
#pragma unroll
    for (int ms = 0; ms < 4; ms++) {
        int r0 = brow + wm * 64 + ms * 16 + gq;
#pragma unroll
        for (int half = 0; half < 2; half++) {
            int row = r0 + half * 8;
            size_t obase;
            if (DST == 1) {
                int b = row >> 12, h = (row >> 6) & 63, w = row & 63;
                obase = ((size_t)(b * HP + h + 1) * WP + (w + 1)) * CC;
            } else {
                obase = (size_t)row * N;
            }
#pragma unroll
            for (int ns = 0; ns < 4; ns++) {
                int col = bcol + wn * 32 + ns * 8 + 2 * tq;
                if (col < N) {
                    float2 v;
                    v.x = d[ms][ns][half * 2 + 0] + bias[col];
                    v.y = d[ms][ns][half * 2 + 1] + bias[col + 1];
                    *(float2*)&C[obase + col] = v;
                }
            }
        }
    }
}

// ---------------------------------------------------------------------------
// Depthwise 3x3 conv + LayerNorm + exact GELU (one block/pixel, thread/channel)
// ---------------------------------------------------------------------------
__global__ __launch_bounds__(256)
void dwlngelu_kernel(const float* __restrict__ in,
                     const float* __restrict__ dwk,
                     const float* __restrict__ dwb,
                     const float* __restrict__ gamma,
                     const float* __restrict__ beta) {
    int p = blockIdx.x;
    int c = threadIdx.x;
    int b = p >> 12, h = (p >> 6) & 63, w = p & 63;

    float s = dwb[c];
#pragma unroll
    for (int ky = 0; ky < 3; ky++) {
        int hh = h + ky - 1;
        if (hh < 0 || hh >= HH) continue;
#pragma unroll
        for (int kx = 0; kx < 3; kx++) {
            int ww = w + kx - 1;
            if (ww < 0 || ww >= WW) continue;
            s += in[((size_t)(b * HH + hh) * WW + ww) * CC + c] *
                 dwk[(ky * 3 + kx) * CC + c];
        }
    }

    __shared__ float rs[256];
    __shared__ float rs2[256];
    rs[c] = s; rs2[c] = s * s;
    __syncthreads();
#pragma unroll
    for (int off = 128; off > 0; off >>= 1) {
        if (c < off) { rs[c] += rs[c + off]; rs2[c] += rs2[c + off]; }
        __syncthreads();
    }
    float mu  = rs[0] * (1.0f / 256.0f);
    float var = rs2[0] * (1.0f / 256.0f) - mu * mu;
    float y = (s - mu) * rsqrtf(var + 1e-6f) * gamma[c] + beta[c];
    g_x1[(size_t)p * CC + c] = 0.5f * y * (1.0f + erff(y * 0.70710678118654752f));
}

// ---------------------------------------------------------------------------
// Softmax over 9 taps per (pixel, group)
// ---------------------------------------------------------------------------
__global__ void mask_softmax_kernel() {
    int i = blockIdx.x * blockDim.x + threadIdx.x;
    if (i >= NPIX * GG) return;
    int p = i >> 3, g = i & 7;
    float* m = g_mask + (size_t)p * 72 + g * 9;
    float v[K2], mx = -1e30f;
#pragma unroll
    for (int k = 0; k < K2; k++) { v[k] = m[k]; mx = fmaxf(mx, v[k]); }
    float den = 0.f;
#pragma unroll
    for (int k = 0; k < K2; k++) { v[k] = __expf(v[k] - mx); den += v[k]; }
    float inv = 1.0f / den;
#pragma unroll
    for (int k = 0; k < K2; k++) m[k] = v[k] * inv;
}

// ---------------------------------------------------------------------------
// Deformable bilinear gather, locality-blocked:
// block = 8 consecutive pixels (same image row) x 1 group; warp = pixel;
// lane = channel. Adjacent warps' sampling windows overlap -> L1 reuse.
// ---------------------------------------------------------------------------
__global__ __launch_bounds__(256)
void deform_sample_kernel() {
    int p    = blockIdx.x * 8 + (threadIdx.x >> 5);
    int g    = blockIdx.y;
    int lane = threadIdx.x & 31;
    int b = p >> 12, h = (p >> 6) & 63, w = p & 63;

    const float* offp = g_off  + (size_t)p * 144 + g * 18;
    const float* mp   = g_mask + (size_t)p * 72  + g * 9;
    const float* base = g_xpad + (size_t)b * HP * WP * CC + g * GCH + lane;

    float acc = 0.f;
#pragma unroll
    for (int k = 0; k < K2; k++) {
        float ox = offp[k * 2 + 0];
        float oy = offp[k * 2 + 1];
        float px = (float)(PADB + w) + (float)(k % 3 - 1) + ox;
        float py = (float)(PADB + h) + (float)(k / 3 - 1) + oy;
        float mk = mp[k];

        float x0f = floorf(px), y0f = floorf(py);
        int x0 = (int)x0f, y0 = (int)y0f;
        float wx = px - x0f, wy = py - y0f;

        float v00 = 0.f, v01 = 0.f, v10 = 0.f, v11 = 0.f;
        bool xv0 = (x0 >= 0) & (x0 < WP);
        bool xv1 = (x0 + 1 >= 0) & (x0 + 1 < WP);
        bool yv0 = (y0 >= 0) & (y0 < HP);
        bool yv1 = (y0 + 1 >= 0) & (y0 + 1 < HP);
        if (yv0) {
            const float* r0 = base + (size_t)y0 * WP * CC;
            if (xv0) v00 = r0[(size_t)x0 * CC];
            if (xv1) v01 = r0[(size_t)(x0 + 1) * CC];
        }
        if (yv1) {
            const float* r1 = base + (size_t)(y0 + 1) * WP * CC;
            if (xv0) v10 = r1[(size_t)x0 * CC];
            if (xv1) v11 = r1[(size_t)(x0 + 1) * CC];
        }
        float sx0 = v00 * (1.f - wx) + v01 * wx;
        float sx1 = v10 * (1.f - wx) + v11 * wx;
        acc += mk * (sx0 * (1.f - wy) + sx1 * wy);
    }
    g_samp[(size_t)p * CC + g * GCH + lane] = acc;
}

// ---------------------------------------------------------------------------
// Launch (kernel launches only)
// ---------------------------------------------------------------------------
extern "C" void kernel_launch(void* const* d_in, const int* in_sizes, int n_in,
                              void* d_out, int out_size) {
    const float* inputs   = (const float*)d_in[0];
    const float* w_in     = (const float*)d_in[1];
    const float* b_in     = (const float*)d_in[2];
    const float* dw_k     = (const float*)d_in[3];
    const float* dw_b     = (const float*)d_in[4];
    const float* ln_gamma = (const float*)d_in[5];
    const float* ln_beta  = (const float*)d_in[6];
    const float* w_off    = (const float*)d_in[7];
    const float* b_off    = (const float*)d_in[8];
    const float* w_mask   = (const float*)d_in[9];
    const float* b_mask   = (const float*)d_in[10];
    const float* w_out    = (const float*)d_in[11];
    const float* b_out    = (const float*)d_in[12];
    float* out = (float*)d_out;

    // 1) zero padded ring
    {
        int total = BATCH * 260 * 64;
        zero_ring_kernel<<<(total + 255) / 256, 256>>>();
    }
    // 2) x_proj GEMM (3xTF32) -> padded layout
    {
        dim3 grid(CC / TBN, NPIX / TBM);
        sgemm_tc<0, 1, true><<<grid, 128>>>(inputs, w_in, b_in, nullptr, CC);
    }
    // 3) depthwise conv + LN + GELU -> g_x1
    dwlngelu_kernel<<<NPIX, 256>>>(inputs, dw_k, dw_b, ln_gamma, ln_beta);
    // 4) offset GEMM (TF32, N=144)
    {
        dim3 grid((144 + TBN - 1) / TBN, NPIX / TBM);
        sgemm_tc<1, 2, false><<<grid, 128>>>(nullptr, w_off, b_off, nullptr, 144);
    }
    // 5) mask GEMM (TF32, N=72) + softmax
    {
        dim3 grid((72 + TBN - 1) / TBN, NPIX / TBM);
        sgemm_tc<1, 3, false><<<grid, 128>>>(nullptr, w_mask, b_mask, nullptr, 72);
        mask_softmax_kernel<<<(NPIX * GG + 255) / 256, 256>>>();
    }
    // 6) deformable bilinear gather
    {
        dim3 grid(NPIX / 8, GG);
        deform_sample_kernel<<<grid, 256>>>();
    }
    // 7) output GEMM (3xTF32)
    {
        dim3 grid(CC / TBN, NPIX / TBM);
        sgemm_tc<2, 0, true><<<grid, 128>>>(nullptr, w_out, b_out, out, CC);
    }
    (void)in_sizes; (void)n_in; (void)out_size;
}

// round 5
// speedup vs baseline: 1.8556x; 1.6606x over previous
#include <cuda_runtime.h>
#include <cuda_bf16.h>
#include <math.h>
#include <stdint.h>

// ---------------------------------------------------------------------------
// Problem constants
// ---------------------------------------------------------------------------
#define BATCH 8
#define HH    64
#define WW    64
#define CC    256
#define GG    8
#define GCH   32
#define K2    9
#define PADB  1
#define HP    66
#define WP    66
#define NPIX  (BATCH*HH*WW) // 32768

// ---------------------------------------------------------------------------
// Scratch (device globals) — referenced ONLY from device code.
// ---------------------------------------------------------------------------
__device__ float g_xpad[BATCH * HP * WP * CC];
__device__ float g_x1  [NPIX * CC];
__device__ float g_off [NPIX * 144];
__device__ float g_mask[NPIX * 72];
__device__ float g_samp[NPIX * CC];

// Pre-split, pre-transposed weights: [n][k] bf16 hi/lo
__device__ __nv_bfloat16 g_wTin_h [CC * CC], g_wTin_l [CC * CC];
__device__ __nv_bfloat16 g_wTom_h [CC * CC], g_wTom_l [CC * CC]; // off(0-143)|mask(144-215)|zero
__device__ __nv_bfloat16 g_wTout_h[CC * CC], g_wTout_l[CC * CC];
__device__ float g_bom[CC]; // packed bias for fused off+mask

// ---------------------------------------------------------------------------
// Weight prep: transpose + bf16 split. grid(256, 3), block 256 (tid = k).
// ---------------------------------------------------------------------------
__global__ void prep_weights(const float* __restrict__ w_in,
                             const float* __restrict__ w_off,
                             const float* __restrict__ w_mask,
                             const float* __restrict__ w_out,
                             const float* __restrict__ b_off,
                             const float* __restrict__ b_mask) {
    int n = blockIdx.x, mat = blockIdx.y, k = threadIdx.x;
    float v;
    __nv_bfloat16 *dh, *dl;
    if (mat == 0)      { v = w_in [k * 256 + n]; dh = g_wTin_h;  dl = g_wTin_l; }
    else if (mat == 2) { v = w_out[k * 256 + n]; dh = g_wTout_h; dl = g_wTout_l; }
    else {
        if (n < 144)      v = w_off [k * 144 + n];
        else if (n < 216) v = w_mask[k * 72 + (n - 144)];
        else              v = 0.f;
        dh = g_wTom_h; dl = g_wTom_l;
        if (n == 0)
            g_bom[k] = (k < 144) ? b_off[k] : (k < 216 ? b_mask[k - 144] : 0.f);
    }
    __nv_bfloat16 h = __float2bfloat16_rn(v);
    __nv_bfloat16 l = __float2bfloat16_rn(v - __bfloat162float(h));
    dh[n * 256 + k] = h;
    dl[n * 256 + k] = l;
}

// ---------------------------------------------------------------------------
// Zero the 1-pixel ring of the padded buffer
// ---------------------------------------------------------------------------
__global__ void zero_ring_kernel() {
    int idx = blockIdx.x * blockDim.x + threadIdx.x;
    const int total = BATCH * 260 * 64;
    if (idx >= total) return;
    int p = idx >> 6, c4 = idx & 63;
    int b = p / 260, r = p % 260;
    int h, w;
    if (r < 66)       { h = 0;       w = r; }
    else if (r < 132) { h = 65;      w = r - 66; }
    else if (r < 196) { h = r - 131; w = 0; }
    else              { h = r - 195; w = 65; }
    size_t a = (((size_t)(b * HP + h) * WP + w) * CC) + c4 * 4;
    *(float4*)(g_xpad + a) = make_float4(0.f, 0.f, 0.f, 0.f);
}

// ---------------------------------------------------------------------------
// MMA / ldmatrix helpers
// ---------------------------------------------------------------------------
#define MMA_BF16(d, a, b)                                                      \
    asm volatile("mma.sync.aligned.m16n8k16.row.col.f32.bf16.bf16.f32 "        \
        "{%0,%1,%2,%3}, {%4,%5,%6,%7}, {%8,%9}, {%0,%1,%2,%3};"                \
        : "+f"((d)[0]), "+f"((d)[1]), "+f"((d)[2]), "+f"((d)[3])               \
        : "r"((a)[0]), "r"((a)[1]), "r"((a)[2]), "r"((a)[3]),                  \
          "r"((b)[0]), "r"((b)[1]))

__device__ __forceinline__ void ldsm4(unsigned* r, uint32_t addr) {
    asm volatile("ldmatrix.sync.aligned.m8n8.x4.shared.b16 {%0,%1,%2,%3}, [%4];"
        : "=r"(r[0]), "=r"(r[1]), "=r"(r[2]), "=r"(r[3]) : "r"(addr));
}

// split fp32x4 -> hi/lo bf16x4 packed as uint2
__device__ __forceinline__ void split4(float4 v, uint2& hi, uint2& lo) {
    __nv_bfloat162 h01 = __floats2bfloat162_rn(v.x, v.y);
    __nv_bfloat162 h23 = __floats2bfloat162_rn(v.z, v.w);
    float2 f01 = __bfloat1622float2(h01);
    float2 f23 = __bfloat1622float2(h23);
    __nv_bfloat162 l01 = __floats2bfloat162_rn(v.x - f01.x, v.y - f01.y);
    __nv_bfloat162 l23 = __floats2bfloat162_rn(v.z - f23.x, v.w - f23.y);
    hi.x = reinterpret_cast<unsigned&>(h01); hi.y = reinterpret_cast<unsigned&>(h23);
    lo.x = reinterpret_cast<unsigned&>(l01); lo.y = reinterpret_cast<unsigned&>(l23);
}

// ---------------------------------------------------------------------------
// bf16 split-precision tensor-core GEMM: C[M,N] = A[M,256] @ B[256,N] + bias
// BM=128, BN=64, BK=32, 256 threads (8 warps, 4x2), warp tile 32x32.
// Smem rows: 32 bf16 padded to 40.
// SRC:  0 ext, 1 g_x1, 2 g_samp
// DST:  0 ext, 1 g_xpad (padded layout), 2 fused off|mask split
// WSEL: 0 w_in (bias ext), 1 off|mask (bias g_bom), 2 w_out (bias ext)
// ---------------------------------------------------------------------------
#define BK   32
#define LDA  40

template<int SRC, int DST, int WSEL>
__global__ __launch_bounds__(256)
void sgemm_bf16(const float* __restrict__ Aext,
                const float* __restrict__ bias_ext,
                float* __restrict__ Cext,
                int N) {
    const float* __restrict__ A =
        (SRC == 0) ? Aext : (SRC == 1) ? (const float*)g_x1 : (const float*)g_samp;
    const __nv_bfloat16* __restrict__ BTh =
        (WSEL == 0) ? g_wTin_h : (WSEL == 1) ? g_wTom_h : g_wTout_h;
    const __nv_bfloat16* __restrict__ BTl =
        (WSEL == 0) ? g_wTin_l : (WSEL == 1) ? g_wTom_l : g_wTout_l;
    const float* __restrict__ bias = (WSEL == 1) ? (const float*)g_bom : bias_ext;

    __shared__ __nv_bfloat16 Ah[128][LDA], Al[128][LDA];
    __shared__ __nv_bfloat16 Bh[64][LDA],  Bl[64][LDA];

    const int tid  = threadIdx.x;
    const int warp = tid >> 5;
    const int lane = tid & 31;
    const int wm = warp >> 1;   // 0..3
    const int wn = warp & 1;    // 0..1
    const int brow = blockIdx.y * 128;
    const int bcol = blockIdx.x * 64;

    const uint32_t ah_base = (uint32_t)__cvta_generic_to_shared(&Ah[0][0]);
    const uint32_t al_base = (uint32_t)__cvta_generic_to_shared(&Al[0][0]);
    const uint32_t bh_base = (uint32_t)__cvta_generic_to_shared(&Bh[0][0]);
    const uint32_t bl_base = (uint32_t)__cvta_generic_to_shared(&Bl[0][0]);

    float d[2][4][4];
#pragma unroll
    for (int i = 0; i < 2; i++)
#pragma unroll
        for (int j = 0; j < 4; j++)
#pragma unroll
            for (int k = 0; k < 4; k++) d[i][j][k] = 0.f;

    float4 pa[4];
    float4 pbh, pbl;

    const int arow0 = tid >> 3;   // 0..31 (+32*i)
    const int akq   = tid & 7;    // float4 index in row
    const int brw   = tid >> 2;   // 0..63
    const int bch   = tid & 3;    // 16B chunk

    auto ldg = [&](int k0) {
#pragma unroll
        for (int i = 0; i < 4; i++)
            pa[i] = *(const float4*)(A + (size_t)(brow + arow0 + 32 * i) * CC + k0 + akq * 4);
        pbh = *(const float4*)(BTh + (size_t)(bcol + brw) * 256 + k0 + bch * 8);
        pbl = *(const float4*)(BTl + (size_t)(bcol + brw) * 256 + k0 + bch * 8);
    };
    auto sts = [&]() {
#pragma unroll
        for (int i = 0; i < 4; i++) {
            uint2 hi, lo;
            split4(pa[i], hi, lo);
            *(uint2*)&Ah[arow0 + 32 * i][akq * 4] = hi;
            *(uint2*)&Al[arow0 + 32 * i][akq * 4] = lo;
        }
        *(float4*)&Bh[brw][bch * 8] = pbh;
        *(float4*)&Bl[brw][bch * 8] = pbl;
    };

    const int t  = lane >> 3;
    const int lr = lane & 7;

    auto compute = [&]() {
#pragma unroll
        for (int kk = 0; kk < 2; kk++) {
            unsigned ahf[2][4], alf[2][4], bhf[4][2], blf[4][2];
#pragma unroll
            for (int ms = 0; ms < 2; ms++) {
                uint32_t aoff = (uint32_t)((wm * 32 + ms * 16 + ((t & 1) << 3) + lr) * (LDA * 2)
                                           + kk * 32 + ((t >> 1) << 4));
                ldsm4(ahf[ms], ah_base + aoff);
                ldsm4(alf[ms], al_base + aoff);
            }
#pragma unroll
            for (int nb = 0; nb < 2; nb++) {
                uint32_t boff = (uint32_t)((wn * 32 + nb * 16 + ((t >> 1) << 3) + lr) * (LDA * 2)
                                           + kk * 32 + ((t & 1) << 4));
                unsigned rh[4], rl[4];
                ldsm4(rh, bh_base + boff);
                ldsm4(rl, bl_base + boff);
                bhf[nb * 2 + 0][0] = rh[0]; bhf[nb * 2 + 0][1] = rh[1];
                bhf[nb * 2 + 1][0] = rh[2]; bhf[nb * 2 + 1][1] = rh[3];
                blf[nb * 2 + 0][0] = rl[0]; blf[nb * 2 + 0][1] = rl[1];
                blf[nb * 2 + 1][0] = rl[2]; blf[nb * 2 + 1][1] = rl[3];
            }
#pragma unroll
            for (int ms = 0; ms < 2; ms++)
#pragma unroll
                for (int ns = 0; ns < 4; ns++) {
                    MMA_BF16(d[ms][ns], ahf[ms], bhf[ns]);
                    MMA_BF16(d[ms][ns], ahf[ms], blf[ns]);
                    MMA_BF16(d[ms][ns], alf[ms], bhf[ns]);
                }
        }
    };

    ldg(0);
    sts();
    __syncthreads();
#pragma unroll 1
    for (int it = 0; it < 8; it++) {
        if (it < 7) ldg((it + 1) * BK);
        compute();
        if (it < 7) {
            __syncthreads();
            sts();
            __syncthreads();
        }
    }

    // epilogue
#pragma unroll
    for (int ms = 0; ms < 2; ms++) {
        int row0 = brow + wm * 32 + ms * 16 + (lane >> 2);
#pragma unroll
        for (int half = 0; half < 2; half++) {
            int row = row0 + half * 8;
#pragma unroll
            for (int ns = 0; ns < 4; ns++) {
                int col = bcol + wn * 32 + ns * 8 + 2 * (lane & 3);
                if (col >= N) continue;
                float2 v;
                v.x = d[ms][ns][half * 2 + 0] + bias[col];
                v.y = d[ms][ns][half * 2 + 1] + bias[col + 1];
                if (DST == 1) {
                    int b = row >> 12, h = (row >> 6) & 63, w = row & 63;
                    size_t ob = ((size_t)(b * HP + h + 1) * WP + (w + 1)) * CC;
                    *(float2*)&g_xpad[ob + col] = v;
                } else if (DST == 2) {
                    if (col < 144)      *(float2*)&g_off [(size_t)row * 144 + col] = v;
                    else                *(float2*)&g_mask[(size_t)row * 72 + col - 144] = v;
                } else {
                    *(float2*)&Cext[(size_t)row * N + col] = v;
                }
            }
        }
    }
}

// ---------------------------------------------------------------------------
// Depthwise 3x3 + LayerNorm + exact GELU. Warp per pixel, shfl reduction.
// ---------------------------------------------------------------------------
__global__ __launch_bounds__(256)
void dwlngelu_kernel(const float* __restrict__ in,
                     const float* __restrict__ dwk,
                     const float* __restrict__ dwb,
                     const float* __restrict__ gamma,
                     const float* __restrict__ beta) {
    int p = blockIdx.x * 8 + (threadIdx.x >> 5);
    int lane = threadIdx.x & 31;
    int b = p >> 12, h = (p >> 6) & 63, w = p & 63;
    int c0 = lane * 4, c1 = 128 + lane * 4;

    float4 s0 = *(const float4*)(dwb + c0);
    float4 s1 = *(const float4*)(dwb + c1);
#pragma unroll
    for (int ky = 0; ky < 3; ky++) {
        int hh = h + ky - 1;
        if (hh < 0 || hh >= HH) continue;
#pragma unroll
        for (int kx = 0; kx < 3; kx++) {
            int ww = w + kx - 1;
            if (ww < 0 || ww >= WW) continue;
            const float* src = in + ((size_t)(b * HH + hh) * WW + ww) * CC;
            const float* kk  = dwk + (ky * 3 + kx) * CC;
            float4 x0 = *(const float4*)(src + c0);
            float4 k0 = *(const float4*)(kk + c0);
            float4 x1 = *(const float4*)(src + c1);
            float4 k1 = *(const float4*)(kk + c1);
            s0.x += x0.x * k0.x; s0.y += x0.y * k0.y; s0.z += x0.z * k0.z; s0.w += x0.w * k0.w;
            s1.x += x1.x * k1.x; s1.y += x1.y * k1.y; s1.z += x1.z * k1.z; s1.w += x1.w * k1.w;
        }
    }
    float sum = s0.x + s0.y + s0.z + s0.w + s1.x + s1.y + s1.z + s1.w;
    float sq  = s0.x*s0.x + s0.y*s0.y + s0.z*s0.z + s0.w*s0.w
              + s1.x*s1.x + s1.y*s1.y + s1.z*s1.z + s1.w*s1.w;
#pragma unroll
    for (int off = 16; off > 0; off >>= 1) {
        sum += __shfl_xor_sync(0xFFFFFFFFu, sum, off);
        sq  += __shfl_xor_sync(0xFFFFFFFFu, sq,  off);
    }
    float mu  = sum * (1.0f / 256.0f);
    float var = sq * (1.0f / 256.0f) - mu * mu;
    float rstd = rsqrtf(var + 1e-6f);

    float4 ga0 = *(const float4*)(gamma + c0), ga1 = *(const float4*)(gamma + c1);
    float4 be0 = *(const float4*)(beta + c0),  be1 = *(const float4*)(beta + c1);
    float* o = g_x1 + (size_t)p * CC;
    float4 r0, r1;
    {
        float y;
        y = (s0.x - mu) * rstd * ga0.x + be0.x; r0.x = 0.5f * y * (1.f + erff(y * 0.70710678f));
        y = (s0.y - mu) * rstd * ga0.y + be0.y; r0.y = 0.5f * y * (1.f + erff(y * 0.70710678f));
        y = (s0.z - mu) * rstd * ga0.z + be0.z; r0.z = 0.5f * y * (1.f + erff(y * 0.70710678f));
        y = (s0.w - mu) * rstd * ga0.w + be0.w; r0.w = 0.5f * y * (1.f + erff(y * 0.70710678f));
        y = (s1.x - mu) * rstd * ga1.x + be1.x; r1.x = 0.5f * y * (1.f + erff(y * 0.70710678f));
        y = (s1.y - mu) * rstd * ga1.y + be1.y; r1.y = 0.5f * y * (1.f + erff(y * 0.70710678f));
        y = (s1.z - mu) * rstd * ga1.z + be1.z; r1.z = 0.5f * y * (1.f + erff(y * 0.70710678f));
        y = (s1.w - mu) * rstd * ga1.w + be1.w; r1.w = 0.5f * y * (1.f + erff(y * 0.70710678f));
    }
    *(float4*)(o + c0) = r0;
    *(float4*)(o + c1) = r1;
}

// ---------------------------------------------------------------------------
// Softmax over 9 taps per (pixel, group)
// ---------------------------------------------------------------------------
__global__ void mask_softmax_kernel() {
    int i = blockIdx.x * blockDim.x + threadIdx.x;
    if (i >= NPIX * GG) return;
    int p = i >> 3, g = i & 7;
    float* m = g_mask + (size_t)p * 72 + g * 9;
    float v[K2], mx = -1e30f;
#pragma unroll
    for (int k = 0; k < K2; k++) { v[k] = m[k]; mx = fmaxf(mx, v[k]); }
    float den = 0.f;
#pragma unroll
    for (int k = 0; k < K2; k++) { v[k] = __expf(v[k] - mx); den += v[k]; }
    float inv = 1.0f / den;
#pragma unroll
    for (int k = 0; k < K2; k++) m[k] = v[k] * inv;
}

// ---------------------------------------------------------------------------
// Deformable bilinear gather, locality-blocked (8 pixels x 1 group per block)
// ---------------------------------------------------------------------------
__global__ __launch_bounds__(256)
void deform_sample_kernel() {
    int p    = blockIdx.x * 8 + (threadIdx.x >> 5);
    int g    = blockIdx.y;
    int lane = threadIdx.x & 31;
    int b = p >> 12, h = (p >> 6) & 63, w = p & 63;

    const float* offp = g_off  + (size_t)p * 144 + g * 18;
    const float* mp   = g_mask + (size_t)p * 72  + g * 9;
    const float* base = g_xpad + (size_t)b * HP * WP * CC + g * GCH + lane;

    float acc = 0.f;
#pragma unroll
    for (int k = 0; k < K2; k++) {
        float ox = offp[k * 2 + 0];
        float oy = offp[k * 2 + 1];
        float px = (float)(PADB + w) + (float)(k % 3 - 1) + ox;
        float py = (float)(PADB + h) + (float)(k / 3 - 1) + oy;
        float mk = mp[k];

        float x0f = floorf(px), y0f = floorf(py);
        int x0 = (int)x0f, y0 = (int)y0f;
        float wx = px - x0f, wy = py - y0f;

        float v00 = 0.f, v01 = 0.f, v10 = 0.f, v11 = 0.f;
        bool xv0 = (x0 >= 0) & (x0 < WP);
        bool xv1 = (x0 + 1 >= 0) & (x0 + 1 < WP);
        bool yv0 = (y0 >= 0) & (y0 < HP);
        bool yv1 = (y0 + 1 >= 0) & (y0 + 1 < HP);
        if (yv0) {
            const float* r0 = base + (size_t)y0 * WP * CC;
            if (xv0) v00 = r0[(size_t)x0 * CC];
            if (xv1) v01 = r0[(size_t)(x0 + 1) * CC];
        }
        if (yv1) {
            const float* r1 = base + (size_t)(y0 + 1) * WP * CC;
            if (xv0) v10 = r1[(size_t)x0 * CC];
            if (xv1) v11 = r1[(size_t)(x0 + 1) * CC];
        }
        float sx0 = v00 * (1.f - wx) + v01 * wx;
        float sx1 = v10 * (1.f - wx) + v11 * wx;
        acc += mk * (sx0 * (1.f - wy) + sx1 * wy);
    }
    g_samp[(size_t)p * CC + g * GCH + lane] = acc;
}

// ---------------------------------------------------------------------------
// Launch (kernel launches only; NO device symbols referenced from host code)
// ---------------------------------------------------------------------------
extern "C" void kernel_launch(void* const* d_in, const int* in_sizes, int n_in,
                              void* d_out, int out_size) {
    const float* inputs   = (const float*)d_in[0];
    const float* w_in     = (const float*)d_in[1];
    const float* b_in     = (const float*)d_in[2];
    const float* dw_k     = (const float*)d_in[3];
    const float* dw_b     = (const float*)d_in[4];
    const float* ln_gamma = (const float*)d_in[5];
    const float* ln_beta  = (const float*)d_in[6];
    const float* w_off    = (const float*)d_in[7];
    const float* b_off    = (const float*)d_in[8];
    const float* w_mask   = (const float*)d_in[9];
    const float* b_mask   = (const float*)d_in[10];
    const float* w_out    = (const float*)d_in[11];
    const float* b_out    = (const float*)d_in[12];
    float* out = (float*)d_out;

    // 0) weight prep (transpose + bf16 split + bias pack)
    {
        dim3 grid(256, 3);
        prep_weights<<<grid, 256>>>(w_in, w_off, w_mask, w_out, b_off, b_mask);
    }
    // 1) zero padded ring
    zero_ring_kernel<<<(BATCH * 260 * 64 + 255) / 256, 256>>>();
    // 2) x_proj GEMM -> padded layout
    {
        dim3 grid(CC / 64, NPIX / 128);
        sgemm_bf16<0, 1, 0><<<grid, 256>>>(inputs, b_in, nullptr, CC);
    }
    // 3) depthwise conv + LN + GELU -> g_x1
    dwlngelu_kernel<<<NPIX / 8, 256>>>(inputs, dw_k, dw_b, ln_gamma, ln_beta);
    // 4) fused offset+mask GEMM (N=216 packed into 256-col weights)
    {
        dim3 grid(256 / 64, NPIX / 128);
        sgemm_bf16<1, 2, 1><<<grid, 256>>>(nullptr, nullptr, nullptr, 216);
    }
    // 5) mask softmax
    mask_softmax_kernel<<<(NPIX * GG + 255) / 256, 256>>>();
    // 6) deformable bilinear gather
    {
        dim3 grid(NPIX / 8, GG);
        deform_sample_kernel<<<grid, 256>>>();
    }
    // 7) output GEMM
    {
        dim3 grid(CC / 64, NPIX / 128);
        sgemm_bf16<2, 0, 2><<<grid, 256>>>(nullptr, b_out, out, CC);
    }
    (void)in_sizes; (void)n_in; (void)out_size;
}

// round 6
// speedup vs baseline: 1.8764x; 1.0112x over previous
#include <cuda_runtime.h>
#include <cuda_bf16.h>
#include <math.h>
#include <stdint.h>

// ---------------------------------------------------------------------------
// Problem constants
// ---------------------------------------------------------------------------
#define BATCH 8
#define HH    64
#define WW    64
#define CC    256
#define GG    8
#define GCH   32
#define K2    9
#define PADB  1
#define HP    66
#define WP    66
#define NPIX  (BATCH*HH*WW) // 32768

// ---------------------------------------------------------------------------
// Scratch (device globals) — referenced ONLY from device code.
// ---------------------------------------------------------------------------
__device__ float g_xpad[BATCH * HP * WP * CC];       // padded x_proj (fp32)
__device__ float g_off [NPIX * 144];                 // offsets
__device__ float g_mask[NPIX * 72];                  // mask logits (softmax in sampler)

// bf16 hi/lo activation buffers (GEMM A operands)
__device__ __nv_bfloat16 g_inh [NPIX * CC], g_inl [NPIX * CC];
__device__ __nv_bfloat16 g_x1h [NPIX * CC], g_x1l [NPIX * CC];
__device__ __nv_bfloat16 g_smh [NPIX * CC], g_sml [NPIX * CC];

// Pre-split, pre-transposed weights: [n][k] bf16 hi/lo
__device__ __nv_bfloat16 g_wTin_h [CC * CC], g_wTin_l [CC * CC];
__device__ __nv_bfloat16 g_wTom_h [CC * CC], g_wTom_l [CC * CC]; // off|mask|zero
__device__ __nv_bfloat16 g_wTout_h[CC * CC], g_wTout_l[CC * CC];
__device__ float g_bom[CC];

// ---------------------------------------------------------------------------
// split helpers
// ---------------------------------------------------------------------------
__device__ __forceinline__ void split4(float4 v, uint2& hi, uint2& lo) {
    __nv_bfloat162 h01 = __floats2bfloat162_rn(v.x, v.y);
    __nv_bfloat162 h23 = __floats2bfloat162_rn(v.z, v.w);
    float2 f01 = __bfloat1622float2(h01);
    float2 f23 = __bfloat1622float2(h23);
    __nv_bfloat162 l01 = __floats2bfloat162_rn(v.x - f01.x, v.y - f01.y);
    __nv_bfloat162 l23 = __floats2bfloat162_rn(v.z - f23.x, v.w - f23.y);
    hi.x = reinterpret_cast<unsigned&>(h01); hi.y = reinterpret_cast<unsigned&>(h23);
    lo.x = reinterpret_cast<unsigned&>(l01); lo.y = reinterpret_cast<unsigned&>(l23);
}

// ---------------------------------------------------------------------------
// Weight prep: transpose + bf16 split. grid(256, 3), block 256 (tid = k).
// ---------------------------------------------------------------------------
__global__ void prep_weights(const float* __restrict__ w_in,
                             const float* __restrict__ w_off,
                             const float* __restrict__ w_mask,
                             const float* __restrict__ w_out,
                             const float* __restrict__ b_off,
                             const float* __restrict__ b_mask) {
    int n = blockIdx.x, mat = blockIdx.y, k = threadIdx.x;
    float v;
    __nv_bfloat16 *dh, *dl;
    if (mat == 0)      { v = w_in [k * 256 + n]; dh = g_wTin_h;  dl = g_wTin_l; }
    else if (mat == 2) { v = w_out[k * 256 + n]; dh = g_wTout_h; dl = g_wTout_l; }
    else {
        if (n < 144)      v = w_off [k * 144 + n];
        else if (n < 216) v = w_mask[k * 72 + (n - 144)];
        else              v = 0.f;
        dh = g_wTom_h; dl = g_wTom_l;
        if (n == 0)
            g_bom[k] = (k < 144) ? b_off[k] : (k < 216 ? b_mask[k - 144] : 0.f);
    }
    __nv_bfloat16 h = __float2bfloat16_rn(v);
    __nv_bfloat16 l = __float2bfloat16_rn(v - __bfloat162float(h));
    dh[n * 256 + k] = h;
    dl[n * 256 + k] = l;
}

// ---------------------------------------------------------------------------
// Convert external inputs -> bf16 hi/lo  (thread = one float4)
// ---------------------------------------------------------------------------
__global__ void convert_inputs(const float* __restrict__ in) {
    int i = blockIdx.x * blockDim.x + threadIdx.x;  // float4 index
    if (i >= NPIX * CC / 4) return;
    float4 v = ((const float4*)in)[i];
    uint2 hi, lo;
    split4(v, hi, lo);
    ((uint2*)g_inh)[i] = hi;
    ((uint2*)g_inl)[i] = lo;
}

// ---------------------------------------------------------------------------
// Zero the 1-pixel ring of the padded buffer
// ---------------------------------------------------------------------------
__global__ void zero_ring_kernel() {
    int idx = blockIdx.x * blockDim.x + threadIdx.x;
    const int total = BATCH * 260 * 64;
    if (idx >= total) return;
    int p = idx >> 6, c4 = idx & 63;
    int b = p / 260, r = p % 260;
    int h, w;
    if (r < 66)       { h = 0;       w = r; }
    else if (r < 132) { h = 65;      w = r - 66; }
    else if (r < 196) { h = r - 131; w = 0; }
    else              { h = r - 195; w = 65; }
    size_t a = (((size_t)(b * HP + h) * WP + w) * CC) + c4 * 4;
    *(float4*)(g_xpad + a) = make_float4(0.f, 0.f, 0.f, 0.f);
}

// ---------------------------------------------------------------------------
// MMA / ldmatrix helpers
// ---------------------------------------------------------------------------
#define MMA_BF16(d, a, b)                                                      \
    asm volatile("mma.sync.aligned.m16n8k16.row.col.f32.bf16.bf16.f32 "        \
        "{%0,%1,%2,%3}, {%4,%5,%6,%7}, {%8,%9}, {%0,%1,%2,%3};"                \
        : "+f"((d)[0]), "+f"((d)[1]), "+f"((d)[2]), "+f"((d)[3])               \
        : "r"((a)[0]), "r"((a)[1]), "r"((a)[2]), "r"((a)[3]),                  \
          "r"((b)[0]), "r"((b)[1]))

__device__ __forceinline__ void ldsm4(unsigned* r, uint32_t addr) {
    asm volatile("ldmatrix.sync.aligned.m8n8.x4.shared.b16 {%0,%1,%2,%3}, [%4];"
        : "=r"(r[0]), "=r"(r[1]), "=r"(r[2]), "=r"(r[3]) : "r"(addr));
}

// ---------------------------------------------------------------------------
// bf16 split-precision tensor-core GEMM: C[M,N] = A[M,256] @ B[256,N] + bias
// BM=128, BN=64, BK=32, 256 threads (8 warps, 4x2), warp tile 32x32.
// A already pre-split bf16 hi/lo in gmem -> pure 16B staging, no conversion.
// SRC:  0 g_in, 1 g_x1, 2 g_sm
// DST:  0 ext, 1 g_xpad (padded layout), 2 fused off|mask split
// WSEL: 0 w_in, 1 off|mask (bias g_bom), 2 w_out
// ---------------------------------------------------------------------------
#define BK   32
#define LDA  40

template<int SRC, int DST, int WSEL>
__global__ __launch_bounds__(256)
void sgemm_bf16(const float* __restrict__ bias_ext,
                float* __restrict__ Cext,
                int N) {
    const __nv_bfloat16* __restrict__ Agh =
        (SRC == 0) ? g_inh : (SRC == 1) ? g_x1h : g_smh;
    const __nv_bfloat16* __restrict__ Agl =
        (SRC == 0) ? g_inl : (SRC == 1) ? g_x1l : g_sml;
    const __nv_bfloat16* __restrict__ BTh =
        (WSEL == 0) ? g_wTin_h : (WSEL == 1) ? g_wTom_h : g_wTout_h;
    const __nv_bfloat16* __restrict__ BTl =
        (WSEL == 0) ? g_wTin_l : (WSEL == 1) ? g_wTom_l : g_wTout_l;
    const float* __restrict__ bias = (WSEL == 1) ? (const float*)g_bom : bias_ext;

    __shared__ __nv_bfloat16 Ah[128][LDA], Al[128][LDA];
    __shared__ __nv_bfloat16 Bh[64][LDA],  Bl[64][LDA];

    const int tid  = threadIdx.x;
    const int warp = tid >> 5;
    const int lane = tid & 31;
    const int wm = warp >> 1;
    const int wn = warp & 1;
    const int brow = blockIdx.y * 128;
    const int bcol = blockIdx.x * 64;

    const uint32_t ah_base = (uint32_t)__cvta_generic_to_shared(&Ah[0][0]);
    const uint32_t al_base = (uint32_t)__cvta_generic_to_shared(&Al[0][0]);
    const uint32_t bh_base = (uint32_t)__cvta_generic_to_shared(&Bh[0][0]);
    const uint32_t bl_base = (uint32_t)__cvta_generic_to_shared(&Bl[0][0]);

    float d[2][4][4];
#pragma unroll
    for (int i = 0; i < 2; i++)
#pragma unroll
        for (int j = 0; j < 4; j++)
#pragma unroll
            for (int k = 0; k < 4; k++) d[i][j][k] = 0.f;

    // A: thread -> row tid>>1, 16 bf16 at col (tid&1)*16 (two uint4 per buf)
    const int arow = tid >> 1;
    const int acol = (tid & 1) * 16;
    // B: thread -> row tid>>2, 8 bf16 at col (tid&3)*8 (one uint4 per buf)
    const int brw  = tid >> 2;
    const int bcl  = (tid & 3) * 8;

    uint4 pah0, pah1, pal0, pal1, pbh, pbl;

    auto ldg = [&](int k0) {
        const __nv_bfloat16* ah = Agh + (size_t)(brow + arow) * 256 + k0 + acol;
        const __nv_bfloat16* al = Agl + (size_t)(brow + arow) * 256 + k0 + acol;
        pah0 = *(const uint4*)ah;       pah1 = *(const uint4*)(ah + 8);
        pal0 = *(const uint4*)al;       pal1 = *(const uint4*)(al + 8);
        pbh = *(const uint4*)(BTh + (size_t)(bcol + brw) * 256 + k0 + bcl);
        pbl = *(const uint4*)(BTl + (size_t)(bcol + brw) * 256 + k0 + bcl);
    };
    auto sts = [&]() {
        *(uint4*)&Ah[arow][acol]     = pah0;
        *(uint4*)&Ah[arow][acol + 8] = pah1;
        *(uint4*)&Al[arow][acol]     = pal0;
        *(uint4*)&Al[arow][acol + 8] = pal1;
        *(uint4*)&Bh[brw][bcl] = pbh;
        *(uint4*)&Bl[brw][bcl] = pbl;
    };

    const int t  = lane >> 3;
    const int lr = lane & 7;

    auto compute = [&]() {
#pragma unroll
        for (int kk = 0; kk < 2; kk++) {
            unsigned ahf[2][4], alf[2][4], bhf[4][2], blf[4][2];
#pragma unroll
            for (int ms = 0; ms < 2; ms++) {
                uint32_t aoff = (uint32_t)((wm * 32 + ms * 16 + ((t & 1) << 3) + lr) * (LDA * 2)
                                           + kk * 32 + ((t >> 1) << 4));
                ldsm4(ahf[ms], ah_base + aoff);
                ldsm4(alf[ms], al_base + aoff);
            }
#pragma unroll
            for (int nb = 0; nb < 2; nb++) {
                uint32_t boff = (uint32_t)((wn * 32 + nb * 16 + ((t >> 1) << 3) + lr) * (LDA * 2)
                                           + kk * 32 + ((t & 1) << 4));
                unsigned rh[4], rl[4];
                ldsm4(rh, bh_base + boff);
                ldsm4(rl, bl_base + boff);
                bhf[nb * 2 + 0][0] = rh[0]; bhf[nb * 2 + 0][1] = rh[1];
                bhf[nb * 2 + 1][0] = rh[2]; bhf[nb * 2 + 1][1] = rh[3];
                blf[nb * 2 + 0][0] = rl[0]; blf[nb * 2 + 0][1] = rl[1];
                blf[nb * 2 + 1][0] = rl[2]; blf[nb * 2 + 1][1] = rl[3];
            }
#pragma unroll
            for (int ms = 0; ms < 2; ms++)
#pragma unroll
                for (int ns = 0; ns < 4; ns++) {
                    MMA_BF16(d[ms][ns], ahf[ms], bhf[ns]);
                    MMA_BF16(d[ms][ns], ahf[ms], blf[ns]);
                    MMA_BF16(d[ms][ns], alf[ms], bhf[ns]);
                }
        }
    };

    ldg(0);
    sts();
    __syncthreads();
#pragma unroll 1
    for (int it = 0; it < 8; it++) {
        if (it < 7) ldg((it + 1) * BK);
        compute();
        if (it < 7) {
            __syncthreads();
            sts();
            __syncthreads();
        }
    }

    // epilogue
#pragma unroll
    for (int ms = 0; ms < 2; ms++) {
        int row0 = brow + wm * 32 + ms * 16 + (lane >> 2);
#pragma unroll
        for (int half = 0; half < 2; half++) {
            int row = row0 + half * 8;
#pragma unroll
            for (int ns = 0; ns < 4; ns++) {
                int col = bcol + wn * 32 + ns * 8 + 2 * (lane & 3);
                if (col >= N) continue;
                float2 v;
                v.x = d[ms][ns][half * 2 + 0] + bias[col];
                v.y = d[ms][ns][half * 2 + 1] + bias[col + 1];
                if (DST == 1) {
                    int b = row >> 12, h = (row >> 6) & 63, w = row & 63;
                    size_t ob = ((size_t)(b * HP + h + 1) * WP + (w + 1)) * CC;
                    *(float2*)&g_xpad[ob + col] = v;
                } else if (DST == 2) {
                    if (col < 144)      *(float2*)&g_off [(size_t)row * 144 + col] = v;
                    else                *(float2*)&g_mask[(size_t)row * 72 + col - 144] = v;
                } else {
                    *(float2*)&Cext[(size_t)row * N + col] = v;
                }
            }
        }
    }
}

// ---------------------------------------------------------------------------
// Depthwise 3x3 + LayerNorm + exact GELU. Warp = 4 consecutive pixels.
// dwk loaded once per warp per ky-row; input columns shared across pixels.
// Output: bf16 hi/lo into g_x1h / g_x1l.
// ---------------------------------------------------------------------------
__global__ __launch_bounds__(256)
void dwlngelu_kernel(const float* __restrict__ in,
                     const float* __restrict__ dwk,
                     const float* __restrict__ dwb,
                     const float* __restrict__ gamma,
                     const float* __restrict__ beta) {
    const int warp = threadIdx.x >> 5;
    const int lane = threadIdx.x & 31;
    const int pb = blockIdx.x * 32 + warp * 4;        // first of 4 pixels
    const int b = pb >> 12, h = (pb >> 6) & 63, w0 = pb & 63;
    const int c0 = lane * 4, c1 = 128 + lane * 4;

    float4 bias0 = *(const float4*)(dwb + c0);
    float4 bias1 = *(const float4*)(dwb + c1);
    float4 a0[4], a1[4];
#pragma unroll
    for (int i = 0; i < 4; i++) { a0[i] = bias0; a1[i] = bias1; }

#pragma unroll
    for (int ky = 0; ky < 3; ky++) {
        int hh = h + ky - 1;
        if (hh < 0 || hh >= HH) continue;
        float4 kw0[3], kw1[3];
#pragma unroll
        for (int kx = 0; kx < 3; kx++) {
            kw0[kx] = *(const float4*)(dwk + (ky * 3 + kx) * CC + c0);
            kw1[kx] = *(const float4*)(dwk + (ky * 3 + kx) * CC + c1);
        }
        const float* row = in + (size_t)(b * HH + hh) * WW * CC;
#pragma unroll
        for (int j = 0; j < 6; j++) {
            int ww = w0 - 1 + j;
            if (ww < 0 || ww >= WW) continue;
            float4 x0 = *(const float4*)(row + (size_t)ww * CC + c0);
            float4 x1 = *(const float4*)(row + (size_t)ww * CC + c1);
#pragma unroll
            for (int i = 0; i < 4; i++) {
                int kx = j - i;
                if (kx < 0 || kx > 2) continue;
                a0[i].x += x0.x * kw0[kx].x; a0[i].y += x0.y * kw0[kx].y;
                a0[i].z += x0.z * kw0[kx].z; a0[i].w += x0.w * kw0[kx].w;
                a1[i].x += x1.x * kw1[kx].x; a1[i].y += x1.y * kw1[kx].y;
                a1[i].z += x1.z * kw1[kx].z; a1[i].w += x1.w * kw1[kx].w;
            }
        }
    }

    float4 ga0 = *(const float4*)(gamma + c0), ga1 = *(const float4*)(gamma + c1);
    float4 be0 = *(const float4*)(beta + c0),  be1 = *(const float4*)(beta + c1);

#pragma unroll
    for (int i = 0; i < 4; i++) {
        float4 s0 = a0[i], s1 = a1[i];
        float sum = s0.x + s0.y + s0.z + s0.w + s1.x + s1.y + s1.z + s1.w;
        float sq  = s0.x*s0.x + s0.y*s0.y + s0.z*s0.z + s0.w*s0.w
                  + s1.x*s1.x + s1.y*s1.y + s1.z*s1.z + s1.w*s1.w;
#pragma unroll
        for (int off = 16; off > 0; off >>= 1) {
            sum += __shfl_xor_sync(0xFFFFFFFFu, sum, off);
            sq  += __shfl_xor_sync(0xFFFFFFFFu, sq,  off);
        }
        float mu  = sum * (1.0f / 256.0f);
        float var = sq * (1.0f / 256.0f) - mu * mu;
        float rstd = rsqrtf(var + 1e-6f);

        float4 r0, r1;
        float y;
        y = (s0.x - mu) * rstd * ga0.x + be0.x; r0.x = 0.5f * y * (1.f + erff(y * 0.70710678118654752f));
        y = (s0.y - mu) * rstd * ga0.y + be0.y; r0.y = 0.5f * y * (1.f + erff(y * 0.70710678118654752f));
        y = (s0.z - mu) * rstd * ga0.z + be0.z; r0.z = 0.5f * y * (1.f + erff(y * 0.70710678118654752f));
        y = (s0.w - mu) * rstd * ga0.w + be0.w; r0.w = 0.5f * y * (1.f + erff(y * 0.70710678118654752f));
        y = (s1.x - mu) * rstd * ga1.x + be1.x; r1.x = 0.5f * y * (1.f + erff(y * 0.70710678118654752f));
        y = (s1.y - mu) * rstd * ga1.y + be1.y; r1.y = 0.5f * y * (1.f + erff(y * 0.70710678118654752f));
        y = (s1.z - mu) * rstd * ga1.z + be1.z; r1.z = 0.5f * y * (1.f + erff(y * 0.70710678118654752f));
        y = (s1.w - mu) * rstd * ga1.w + be1.w; r1.w = 0.5f * y * (1.f + erff(y * 0.70710678118654752f));

        size_t ob = (size_t)(pb + i) * CC;
        uint2 h0, l0, h1, l1;
        split4(r0, h0, l0);
        split4(r1, h1, l1);
        *(uint2*)&g_x1h[ob + c0] = h0;  *(uint2*)&g_x1l[ob + c0] = l0;
        *(uint2*)&g_x1h[ob + c1] = h1;  *(uint2*)&g_x1l[ob + c1] = l1;
    }
}

// ---------------------------------------------------------------------------
// Deformable bilinear gather + inline softmax.
// Warp = (pixel, group). lane = (corner q = lane>>3, channel chunk cc = lane&7).
// Per tap: ONE warp-wide LDG.128 (4 corners x 8 float4 chunks), weight in regs,
// final 2-level butterfly combines corners. Output bf16 hi/lo.
// ---------------------------------------------------------------------------
__global__ __launch_bounds__(256)
void deform_sample_kernel() {
    const int p    = blockIdx.x * 8 + (threadIdx.x >> 5);
    const int g    = blockIdx.y;
    const int lane = threadIdx.x & 31;
    const int q    = lane >> 3;        // corner 0..3
    const int cc   = lane & 7;         // float4 chunk 0..7
    const int qx = q & 1, qy = q >> 1;
    const int b = p >> 12, h = (p >> 6) & 63, w = p & 63;

    const float* offp = g_off  + (size_t)p * 144 + g * 18;
    const float* mp   = g_mask + (size_t)p * 72  + g * 9;
    const float* base = g_xpad + (size_t)b * HP * WP * CC + g * GCH + cc * 4;

    // inline softmax over the 9 logits (redundant per lane; broadcast loads)
    float mk[K2], mx = -1e30f;
#pragma unroll
    for (int k = 0; k < K2; k++) { mk[k] = mp[k]; mx = fmaxf(mx, mk[k]); }
    float den = 0.f;
#pragma unroll
    for (int k = 0; k < K2; k++) { mk[k] = __expf(mk[k] - mx); den += mk[k]; }
    float inv = 1.0f / den;

    float4 acc = make_float4(0.f, 0.f, 0.f, 0.f);
#pragma unroll
    for (int k = 0; k < K2; k++) {
        float px = (float)(PADB + w) + (float)(k % 3 - 1) + offp[k * 2 + 0];
        float py = (float)(PADB + h) + (float)(k / 3 - 1) + offp[k * 2 + 1];
        float x0f = floorf(px), y0f = floorf(py);
        int xq = (int)x0f + qx, yq = (int)y0f + qy;
        float wx = px - x0f, wy = py - y0f;
        float wq = (qx ? wx : 1.f - wx) * (qy ? wy : 1.f - wy) * (mk[k] * inv);

        if (xq >= 0 && xq < WP && yq >= 0 && yq < HP) {
            float4 v = *(const float4*)(base + ((size_t)yq * WP + xq) * CC);
            acc.x += v.x * wq; acc.y += v.y * wq;
            acc.z += v.z * wq; acc.w += v.w * wq;
        }
    }
    // combine the 4 corners (lanes differing in bits 3,4)
#pragma unroll
    for (int off = 8; off <= 16; off <<= 1) {
        acc.x += __shfl_xor_sync(0xFFFFFFFFu, acc.x, off);
        acc.y += __shfl_xor_sync(0xFFFFFFFFu, acc.y, off);
        acc.z += __shfl_xor_sync(0xFFFFFFFFu, acc.z, off);
        acc.w += __shfl_xor_sync(0xFFFFFFFFu, acc.w, off);
    }
    if (lane < 8) {
        uint2 hi, lo;
        split4(acc, hi, lo);
        size_t ob = (size_t)p * CC + g * GCH + cc * 4;
        *(uint2*)&g_smh[ob] = hi;
        *(uint2*)&g_sml[ob] = lo;
    }
}

// ---------------------------------------------------------------------------
// Launch (kernel launches only; NO device symbols referenced from host code)
// ---------------------------------------------------------------------------
extern "C" void kernel_launch(void* const* d_in, const int* in_sizes, int n_in,
                              void* d_out, int out_size) {
    const float* inputs   = (const float*)d_in[0];
    const float* w_in     = (const float*)d_in[1];
    const float* b_in     = (const float*)d_in[2];
    const float* dw_k     = (const float*)d_in[3];
    const float* dw_b     = (const float*)d_in[4];
    const float* ln_gamma = (const float*)d_in[5];
    const float* ln_beta  = (const float*)d_in[6];
    const float* w_off    = (const float*)d_in[7];
    const float* b_off    = (const float*)d_in[8];
    const float* w_mask   = (const float*)d_in[9];
    const float* b_mask   = (const float*)d_in[10];
    const float* w_out    = (const float*)d_in[11];
    const float* b_out    = (const float*)d_in[12];
    float* out = (float*)d_out;

    // 0) weight prep + input split + ring zero
    {
        dim3 grid(256, 3);
        prep_weights<<<grid, 256>>>(w_in, w_off, w_mask, w_out, b_off, b_mask);
    }
    convert_inputs<<<(NPIX * CC / 4 + 255) / 256, 256>>>(inputs);
    zero_ring_kernel<<<(BATCH * 260 * 64 + 255) / 256, 256>>>();
    // 1) x_proj GEMM -> padded layout
    {
        dim3 grid(CC / 64, NPIX / 128);
        sgemm_bf16<0, 1, 0><<<grid, 256>>>(b_in, nullptr, CC);
    }
    // 2) depthwise conv + LN + GELU -> g_x1h/l
    dwlngelu_kernel<<<NPIX / 32, 256>>>(inputs, dw_k, dw_b, ln_gamma, ln_beta);
    // 3) fused offset+mask GEMM (N=216 packed into 256-col weights)
    {
        dim3 grid(256 / 64, NPIX / 128);
        sgemm_bf16<1, 2, 1><<<grid, 256>>>(nullptr, nullptr, 216);
    }
    // 4) deformable bilinear gather (+ inline softmax) -> g_smh/l
    {
        dim3 grid(NPIX / 8, GG);
        deform_sample_kernel<<<grid, 256>>>();
    }
    // 5) output GEMM
    {
        dim3 grid(CC / 64, NPIX / 128);
        sgemm_bf16<2, 0, 2><<<grid, 256>>>(b_out, out, CC);
    }
    (void)in_sizes; (void)n_in; (void)out_size;
}

// round 9
// speedup vs baseline: 2.0122x; 1.0724x over previous
#include <cuda_runtime.h>
#include <cuda_bf16.h>
#include <math.h>
#include <stdint.h>

// ---------------------------------------------------------------------------
// Problem constants
// ---------------------------------------------------------------------------
#define BATCH 8
#define HH    64
#define WW    64
#define CC    256
#define GG    8
#define GCH   32
#define K2    9
#define PADB  1
#define HP    66
#define WP    66
#define NPIX  (BATCH*HH*WW) // 32768

// ---------------------------------------------------------------------------
// Scratch (device globals) — referenced ONLY from device code.
// ---------------------------------------------------------------------------
__device__ float g_xpad[BATCH * HP * WP * CC];       // padded x_proj (fp32)
__device__ float g_off [NPIX * 144];                 // offsets
__device__ float g_mask[NPIX * 72];                  // mask logits (softmax in sampler)

// bf16 hi/lo activation buffers (GEMM A operands)
__device__ __nv_bfloat16 g_inh [NPIX * CC], g_inl [NPIX * CC];
__device__ __nv_bfloat16 g_x1h [NPIX * CC], g_x1l [NPIX * CC];
__device__ __nv_bfloat16 g_smh [NPIX * CC], g_sml [NPIX * CC];

// Pre-split, pre-transposed weights: [n][k] bf16 hi/lo
__device__ __nv_bfloat16 g_wTin_h [CC * CC], g_wTin_l [CC * CC];
__device__ __nv_bfloat16 g_wTom_h [CC * CC], g_wTom_l [CC * CC]; // off|mask|zero
__device__ __nv_bfloat16 g_wTout_h[CC * CC], g_wTout_l[CC * CC];
__device__ float g_bom[CC];

// ---------------------------------------------------------------------------
// split helpers
// ---------------------------------------------------------------------------
__device__ __forceinline__ void split4(float4 v, uint2& hi, uint2& lo) {
    __nv_bfloat162 h01 = __floats2bfloat162_rn(v.x, v.y);
    __nv_bfloat162 h23 = __floats2bfloat162_rn(v.z, v.w);
    float2 f01 = __bfloat1622float2(h01);
    float2 f23 = __bfloat1622float2(h23);
    __nv_bfloat162 l01 = __floats2bfloat162_rn(v.x - f01.x, v.y - f01.y);
    __nv_bfloat162 l23 = __floats2bfloat162_rn(v.z - f23.x, v.w - f23.y);
    hi.x = reinterpret_cast<unsigned&>(h01); hi.y = reinterpret_cast<unsigned&>(h23);
    lo.x = reinterpret_cast<unsigned&>(l01); lo.y = reinterpret_cast<unsigned&>(l23);
}

// ---------------------------------------------------------------------------
// Weight prep: transpose + bf16 split. grid(256, 3), block 256 (tid = k).
// ---------------------------------------------------------------------------
__global__ void prep_weights(const float* __restrict__ w_in,
                             const float* __restrict__ w_off,
                             const float* __restrict__ w_mask,
                             const float* __restrict__ w_out,
                             const float* __restrict__ b_off,
                             const float* __restrict__ b_mask) {
    int n = blockIdx.x, mat = blockIdx.y, k = threadIdx.x;
    float v;
    __nv_bfloat16 *dh, *dl;
    if (mat == 0)      { v = w_in [k * 256 + n]; dh = g_wTin_h;  dl = g_wTin_l; }
    else if (mat == 2) { v = w_out[k * 256 + n]; dh = g_wTout_h; dl = g_wTout_l; }
    else {
        if (n < 144)      v = w_off [k * 144 + n];
        else if (n < 216) v = w_mask[k * 72 + (n - 144)];
        else              v = 0.f;
        dh = g_wTom_h; dl = g_wTom_l;
        if (n == 0)
            g_bom[k] = (k < 144) ? b_off[k] : (k < 216 ? b_mask[k - 144] : 0.f);
    }
    __nv_bfloat16 h = __float2bfloat16_rn(v);
    __nv_bfloat16 l = __float2bfloat16_rn(v - __bfloat162float(h));
    dh[n * 256 + k] = h;
    dl[n * 256 + k] = l;
}

// ---------------------------------------------------------------------------
// Convert external inputs -> bf16 hi/lo  (thread = one float4)
// ---------------------------------------------------------------------------
__global__ void convert_inputs(const float* __restrict__ in) {
    int i = blockIdx.x * blockDim.x + threadIdx.x;
    if (i >= NPIX * CC / 4) return;
    float4 v = ((const float4*)in)[i];
    uint2 hi, lo;
    split4(v, hi, lo);
    ((uint2*)g_inh)[i] = hi;
    ((uint2*)g_inl)[i] = lo;
}

// ---------------------------------------------------------------------------
// Zero the 1-pixel ring of the padded buffer
// ---------------------------------------------------------------------------
__global__ void zero_ring_kernel() {
    int idx = blockIdx.x * blockDim.x + threadIdx.x;
    const int total = BATCH * 260 * 64;
    if (idx >= total) return;
    int p = idx >> 6, c4 = idx & 63;
    int b = p / 260, r = p % 260;
    int h, w;
    if (r < 66)       { h = 0;       w = r; }
    else if (r < 132) { h = 65;      w = r - 66; }
    else if (r < 196) { h = r - 131; w = 0; }
    else              { h = r - 195; w = 65; }
    size_t a = (((size_t)(b * HP + h) * WP + w) * CC) + c4 * 4;
    *(float4*)(g_xpad + a) = make_float4(0.f, 0.f, 0.f, 0.f);
}

// ---------------------------------------------------------------------------
// MMA / ldmatrix / cp.async helpers
// ---------------------------------------------------------------------------
#define MMA_BF16(d, a, b)                                                      \
    asm volatile("mma.sync.aligned.m16n8k16.row.col.f32.bf16.bf16.f32 "        \
        "{%0,%1,%2,%3}, {%4,%5,%6,%7}, {%8,%9}, {%0,%1,%2,%3};"                \
        : "+f"((d)[0]), "+f"((d)[1]), "+f"((d)[2]), "+f"((d)[3])               \
        : "r"((a)[0]), "r"((a)[1]), "r"((a)[2]), "r"((a)[3]),                  \
          "r"((b)[0]), "r"((b)[1]))

__device__ __forceinline__ void ldsm4(unsigned* r, uint32_t addr) {
    asm volatile("ldmatrix.sync.aligned.m8n8.x4.shared.b16 {%0,%1,%2,%3}, [%4];"
        : "=r"(r[0]), "=r"(r[1]), "=r"(r[2]), "=r"(r[3]) : "r"(addr));
}

__device__ __forceinline__ void cp16(uint32_t s, const void* g) {
    asm volatile("cp.async.cg.shared.global [%0], [%1], 16;" :: "r"(s), "l"(g));
}
__device__ __forceinline__ void cp_commit() {
    asm volatile("cp.async.commit_group;");
}
template<int N>
__device__ __forceinline__ void cp_wait() {
    asm volatile("cp.async.wait_group %0;" :: "n"(N));
}

// ---------------------------------------------------------------------------
// bf16 split-precision tensor-core GEMM with cp.async 2-stage pipeline.
// C[M,N] = A[M,256] @ B[256,N] + bias
// BM=64, BN=64, BK=32, 256 threads (8 warps 4x2), warp tile 16x32.
// SMEM stage (bytes): Ah@0 (64x40bf16=5120), Al@5120, Bh@10240, Bl@15360
// stage 20480B, 2 stages = 40960B < 48KB static limit.
// SRC:  0 g_in, 1 g_x1, 2 g_sm
// DST:  0 ext, 1 g_xpad (padded layout), 2 fused off|mask split
// WSEL: 0 w_in, 1 off|mask (bias g_bom), 2 w_out
// ---------------------------------------------------------------------------
#define BK   32
#define LDA  40
#define ST_AH 0
#define ST_AL 5120
#define ST_BH 10240
#define ST_BL 15360
#define ST_SZ 20480

template<int SRC, int DST, int WSEL>
__global__ __launch_bounds__(256)
void sgemm_bf16(const float* __restrict__ bias_ext,
                float* __restrict__ Cext,
                int N) {
    const __nv_bfloat16* __restrict__ Agh =
        (SRC == 0) ? g_inh : (SRC == 1) ? g_x1h : g_smh;
    const __nv_bfloat16* __restrict__ Agl =
        (SRC == 0) ? g_inl : (SRC == 1) ? g_x1l : g_sml;
    const __nv_bfloat16* __restrict__ BTh =
        (WSEL == 0) ? g_wTin_h : (WSEL == 1) ? g_wTom_h : g_wTout_h;
    const __nv_bfloat16* __restrict__ BTl =
        (WSEL == 0) ? g_wTin_l : (WSEL == 1) ? g_wTom_l : g_wTout_l;
    const float* __restrict__ bias = (WSEL == 1) ? (const float*)g_bom : bias_ext;

    __shared__ __align__(16) char smem[2 * ST_SZ];
    const uint32_t s_base = (uint32_t)__cvta_generic_to_shared(smem);

    const int tid  = threadIdx.x;
    const int warp = tid >> 5;
    const int lane = tid & 31;
    const int wm = warp >> 1;   // 0..3  (16-row slice)
    const int wn = warp & 1;    // 0..1  (32-col slice)
    const int brow = blockIdx.y * 64;
    const int bcol = blockIdx.x * 64;

    float d[4][4];
#pragma unroll
    for (int j = 0; j < 4; j++)
#pragma unroll
        for (int k = 0; k < 4; k++) d[j][k] = 0.f;

    // cp.async chunk mapping: each of A-hi/A-lo/B-hi/B-lo = 64 rows x 4 chunks
    // of 16B = 256 chunks; thread handles chunk tid in each buffer.
    const int cr = tid >> 2;            // row 0..63
    const int ck = (tid & 3) * 8;       // bf16 col 0/8/16/24

    auto ldgsts = [&](int kidx, int st) {
        int k0 = kidx * BK;
        uint32_t sb = s_base + st * ST_SZ;
        uint32_t ds = cr * (LDA * 2) + ck * 2;
        cp16(sb + ST_AH + ds, Agh + (size_t)(brow + cr) * 256 + k0 + ck);
        cp16(sb + ST_AL + ds, Agl + (size_t)(brow + cr) * 256 + k0 + ck);
        cp16(sb + ST_BH + ds, BTh + (size_t)(bcol + cr) * 256 + k0 + ck);
        cp16(sb + ST_BL + ds, BTl + (size_t)(bcol + cr) * 256 + k0 + ck);
    };

    const int t  = lane >> 3;
    const int lr = lane & 7;

    auto compute = [&](int st) {
        uint32_t sb = s_base + st * ST_SZ;
#pragma unroll
        for (int kk = 0; kk < 2; kk++) {
            unsigned ahf[4], alf[4], bhf[4][2], blf[4][2];
            {
                uint32_t aoff = (uint32_t)((wm * 16 + ((t & 1) << 3) + lr) * (LDA * 2)
                                           + kk * 32 + ((t >> 1) << 4));
                ldsm4(ahf, sb + ST_AH + aoff);
                ldsm4(alf, sb + ST_AL + aoff);
            }
#pragma unroll
            for (int nb = 0; nb < 2; nb++) {
                uint32_t boff = (uint32_t)((wn * 32 + nb * 16 + ((t >> 1) << 3) + lr) * (LDA * 2)
                                           + kk * 32 + ((t & 1) << 4));
                unsigned rh[4], rl[4];
                ldsm4(rh, sb + ST_BH + boff);
                ldsm4(rl, sb + ST_BL + boff);
                bhf[nb * 2 + 0][0] = rh[0]; bhf[nb * 2 + 0][1] = rh[1];
                bhf[nb * 2 + 1][0] = rh[2]; bhf[nb * 2 + 1][1] = rh[3];
                blf[nb * 2 + 0][0] = rl[0]; blf[nb * 2 + 0][1] = rl[1];
                blf[nb * 2 + 1][0] = rl[2]; blf[nb * 2 + 1][1] = rl[3];
            }
#pragma unroll
            for (int ns = 0; ns < 4; ns++) {
                MMA_BF16(d[ns], ahf, bhf[ns]);
                MMA_BF16(d[ns], ahf, blf[ns]);
                MMA_BF16(d[ns], alf, bhf[ns]);
            }
        }
    };

    // pipeline: 8 k-iterations, 2 stages
    ldgsts(0, 0); cp_commit();
    ldgsts(1, 1); cp_commit();
    cp_wait<1>();
    __syncthreads();
    for (int it = 0; it < 8; it++) {
        compute(it & 1);
        __syncthreads();
        if (it + 2 < 8) {
            ldgsts(it + 2, it & 1); cp_commit();
            cp_wait<1>();
        } else {
            cp_wait<0>();
        }
        __syncthreads();
    }

    // epilogue
    {
        int row0 = brow + wm * 16 + (lane >> 2);
#pragma unroll
        for (int half = 0; half < 2; half++) {
            int row = row0 + half * 8;
#pragma unroll
            for (int ns = 0; ns < 4; ns++) {
                int col = bcol + wn * 32 + ns * 8 + 2 * (lane & 3);
                if (col >= N) continue;
                float2 v;
                v.x = d[ns][half * 2 + 0] + bias[col];
                v.y = d[ns][half * 2 + 1] + bias[col + 1];
                if (DST == 1) {
                    int b = row >> 12, h = (row >> 6) & 63, w = row & 63;
                    size_t ob = ((size_t)(b * HP + h + 1) * WP + (w + 1)) * CC;
                    *(float2*)&g_xpad[ob + col] = v;
                } else if (DST == 2) {
                    if (col < 144)      *(float2*)&g_off [(size_t)row * 144 + col] = v;
                    else                *(float2*)&g_mask[(size_t)row * 72 + col - 144] = v;
                } else {
                    *(float2*)&Cext[(size_t)row * N + col] = v;
                }
            }
        }
    }
}

// ---------------------------------------------------------------------------
// Depthwise 3x3 + LayerNorm + exact GELU. Warp = 4 consecutive pixels.
// ---------------------------------------------------------------------------
__global__ __launch_bounds__(256)
void dwlngelu_kernel(const float* __restrict__ in,
                     const float* __restrict__ dwk,
                     const float* __restrict__ dwb,
                     const float* __restrict__ gamma,
                     const float* __restrict__ beta) {
    const int warp = threadIdx.x >> 5;
    const int lane = threadIdx.x & 31;
    const int pb = blockIdx.x * 32 + warp * 4;
    const int b = pb >> 12, h = (pb >> 6) & 63, w0 = pb & 63;
    const int c0 = lane * 4, c1 = 128 + lane * 4;

    float4 bias0 = *(const float4*)(dwb + c0);
    float4 bias1 = *(const float4*)(dwb + c1);
    float4 a0[4], a1[4];
#pragma unroll
    for (int i = 0; i < 4; i++) { a0[i] = bias0; a1[i] = bias1; }

#pragma unroll
    for (int ky = 0; ky < 3; ky++) {
        int hh = h + ky - 1;
        if (hh < 0 || hh >= HH) continue;
        float4 kw0[3], kw1[3];
#pragma unroll
        for (int kx = 0; kx < 3; kx++) {
            kw0[kx] = *(const float4*)(dwk + (ky * 3 + kx) * CC + c0);
            kw1[kx] = *(const float4*)(dwk + (ky * 3 + kx) * CC + c1);
        }
        const float* row = in + (size_t)(b * HH + hh) * WW * CC;
#pragma unroll
        for (int j = 0; j < 6; j++) {
            int ww = w0 - 1 + j;
            if (ww < 0 || ww >= WW) continue;
            float4 x0 = *(const float4*)(row + (size_t)ww * CC + c0);
            float4 x1 = *(const float4*)(row + (size_t)ww * CC + c1);
#pragma unroll
            for (int i = 0; i < 4; i++) {
                int kx = j - i;
                if (kx < 0 || kx > 2) continue;
                a0[i].x += x0.x * kw0[kx].x; a0[i].y += x0.y * kw0[kx].y;
                a0[i].z += x0.z * kw0[kx].z; a0[i].w += x0.w * kw0[kx].w;
                a1[i].x += x1.x * kw1[kx].x; a1[i].y += x1.y * kw1[kx].y;
                a1[i].z += x1.z * kw1[kx].z; a1[i].w += x1.w * kw1[kx].w;
            }
        }
    }

    float4 ga0 = *(const float4*)(gamma + c0), ga1 = *(const float4*)(gamma + c1);
    float4 be0 = *(const float4*)(beta + c0),  be1 = *(const float4*)(beta + c1);

#pragma unroll
    for (int i = 0; i < 4; i++) {
        float4 s0 = a0[i], s1 = a1[i];
        float sum = s0.x + s0.y + s0.z + s0.w + s1.x + s1.y + s1.z + s1.w;
        float sq  = s0.x*s0.x + s0.y*s0.y + s0.z*s0.z + s0.w*s0.w
                  + s1.x*s1.x + s1.y*s1.y + s1.z*s1.z + s1.w*s1.w;
#pragma unroll
        for (int off = 16; off > 0; off >>= 1) {
            sum += __shfl_xor_sync(0xFFFFFFFFu, sum, off);
            sq  += __shfl_xor_sync(0xFFFFFFFFu, sq,  off);
        }
        float mu  = sum * (1.0f / 256.0f);
        float var = sq * (1.0f / 256.0f) - mu * mu;
        float rstd = rsqrtf(var + 1e-6f);

        float4 r0, r1;
        float y;
        y = (s0.x - mu) * rstd * ga0.x + be0.x; r0.x = 0.5f * y * (1.f + erff(y * 0.70710678118654752f));
        y = (s0.y - mu) * rstd * ga0.y + be0.y; r0.y = 0.5f * y * (1.f + erff(y * 0.70710678118654752f));
        y = (s0.z - mu) * rstd * ga0.z + be0.z; r0.z = 0.5f * y * (1.f + erff(y * 0.70710678118654752f));
        y = (s0.w - mu) * rstd * ga0.w + be0.w; r0.w = 0.5f * y * (1.f + erff(y * 0.70710678118654752f));
        y = (s1.x - mu) * rstd * ga1.x + be1.x; r1.x = 0.5f * y * (1.f + erff(y * 0.70710678118654752f));
        y = (s1.y - mu) * rstd * ga1.y + be1.y; r1.y = 0.5f * y * (1.f + erff(y * 0.70710678118654752f));
        y = (s1.z - mu) * rstd * ga1.z + be1.z; r1.z = 0.5f * y * (1.f + erff(y * 0.70710678118654752f));
        y = (s1.w - mu) * rstd * ga1.w + be1.w; r1.w = 0.5f * y * (1.f + erff(y * 0.70710678118654752f));

        size_t ob = (size_t)(pb + i) * CC;
        uint2 h0, l0, h1, l1;
        split4(r0, h0, l0);
        split4(r1, h1, l1);
        *(uint2*)&g_x1h[ob + c0] = h0;  *(uint2*)&g_x1l[ob + c0] = l0;
        *(uint2*)&g_x1h[ob + c1] = h1;  *(uint2*)&g_x1l[ob + c1] = l1;
    }
}

// ---------------------------------------------------------------------------
// Deformable bilinear gather + inline softmax.
// Warp = (pixel, group). lane = (corner q, channel chunk cc).
// ---------------------------------------------------------------------------
__global__ __launch_bounds__(256)
void deform_sample_kernel() {
    const int p    = blockIdx.x * 8 + (threadIdx.x >> 5);
    const int g    = blockIdx.y;
    const int lane = threadIdx.x & 31;
    const int q    = lane >> 3;
    const int cc   = lane & 7;
    const int qx = q & 1, qy = q >> 1;
    const int b = p >> 12, h = (p >> 6) & 63, w = p & 63;

    const float* offp = g_off  + (size_t)p * 144 + g * 18;
    const float* mp   = g_mask + (size_t)p * 72  + g * 9;
    const float* base = g_xpad + (size_t)b * HP * WP * CC + g * GCH + cc * 4;

    float mk[K2], mx = -1e30f;
#pragma unroll
    for (int k = 0; k < K2; k++) { mk[k] = mp[k]; mx = fmaxf(mx, mk[k]); }
    float den = 0.f;
#pragma unroll
    for (int k = 0; k < K2; k++) { mk[k] = __expf(mk[k] - mx); den += mk[k]; }
    float inv = 1.0f / den;

    float4 acc = make_float4(0.f, 0.f, 0.f, 0.f);
#pragma unroll
    for (int k = 0; k < K2; k++) {
        float px = (float)(PADB + w) + (float)(k % 3 - 1) + offp[k * 2 + 0];
        float py = (float)(PADB + h) + (float)(k / 3 - 1) + offp[k * 2 + 1];
        float x0f = floorf(px), y0f = floorf(py);
        int xq = (int)x0f + qx, yq = (int)y0f + qy;
        float wx = px - x0f, wy = py - y0f;
        float wq = (qx ? wx : 1.f - wx) * (qy ? wy : 1.f - wy) * (mk[k] * inv);

        if (xq >= 0 && xq < WP && yq >= 0 && yq < HP) {
            float4 v = *(const float4*)(base + ((size_t)yq * WP + xq) * CC);
            acc.x += v.x * wq; acc.y += v.y * wq;
            acc.z += v.z * wq; acc.w += v.w * wq;
        }
    }
#pragma unroll
    for (int off = 8; off <= 16; off <<= 1) {
        acc.x += __shfl_xor_sync(0xFFFFFFFFu, acc.x, off);
        acc.y += __shfl_xor_sync(0xFFFFFFFFu, acc.y, off);
        acc.z += __shfl_xor_sync(0xFFFFFFFFu, acc.z, off);
        acc.w += __shfl_xor_sync(0xFFFFFFFFu, acc.w, off);
    }
    if (lane < 8) {
        uint2 hi, lo;
        split4(acc, hi, lo);
        size_t ob = (size_t)p * CC + g * GCH + cc * 4;
        *(uint2*)&g_smh[ob] = hi;
        *(uint2*)&g_sml[ob] = lo;
    }
}

// ---------------------------------------------------------------------------
// Launch (kernel launches only; NO device symbols referenced from host code)
// ---------------------------------------------------------------------------
extern "C" void kernel_launch(void* const* d_in, const int* in_sizes, int n_in,
                              void* d_out, int out_size) {
    const float* inputs   = (const float*)d_in[0];
    const float* w_in     = (const float*)d_in[1];
    const float* b_in     = (const float*)d_in[2];
    const float* dw_k     = (const float*)d_in[3];
    const float* dw_b     = (const float*)d_in[4];
    const float* ln_gamma = (const float*)d_in[5];
    const float* ln_beta  = (const float*)d_in[6];
    const float* w_off    = (const float*)d_in[7];
    const float* b_off    = (const float*)d_in[8];
    const float* w_mask   = (const float*)d_in[9];
    const float* b_mask   = (const float*)d_in[10];
    const float* w_out    = (const float*)d_in[11];
    const float* b_out    = (const float*)d_in[12];
    float* out = (float*)d_out;

    {
        dim3 grid(256, 3);
        prep_weights<<<grid, 256>>>(w_in, w_off, w_mask, w_out, b_off, b_mask);
    }
    convert_inputs<<<(NPIX * CC / 4 + 255) / 256, 256>>>(inputs);
    zero_ring_kernel<<<(BATCH * 260 * 64 + 255) / 256, 256>>>();
    {
        dim3 grid(CC / 64, NPIX / 64);
        sgemm_bf16<0, 1, 0><<<grid, 256>>>(b_in, nullptr, CC);
    }
    dwlngelu_kernel<<<NPIX / 32, 256>>>(inputs, dw_k, dw_b, ln_gamma, ln_beta);
    {
        dim3 grid(256 / 64, NPIX / 64);
        sgemm_bf16<1, 2, 1><<<grid, 256>>>(nullptr, nullptr, 216);
    }
    {
        dim3 grid(NPIX / 8, GG);
        deform_sample_kernel<<<grid, 256>>>();
    }
    {
        dim3 grid(CC / 64, NPIX / 64);
        sgemm_bf16<2, 0, 2><<<grid, 256>>>(b_out, out, CC);
    }
    (void)in_sizes; (void)n_in; (void)out_size;
}

// round 13
// speedup vs baseline: 2.0743x; 1.0309x over previous
#include <cuda_runtime.h>
#include <cuda_bf16.h>
#include <math.h>
#include <stdint.h>

// ---------------------------------------------------------------------------
// Problem constants
// ---------------------------------------------------------------------------
#define BATCH 8
#define HH    64
#define WW    64
#define CC    256
#define GG    8
#define GCH   32
#define K2    9
#define PADB  1
#define HP    66
#define WP    66
#define NPIX  (BATCH*HH*WW) // 32768

// ---------------------------------------------------------------------------
// Scratch (device globals) — referenced ONLY from device code.
// ---------------------------------------------------------------------------
__device__ float g_xpad[BATCH * HP * WP * CC];       // padded x_proj (fp32)
__device__ float g_off [NPIX * 144];                 // offsets
__device__ float g_mask[NPIX * 72];                  // mask logits (softmax in sampler)

// bf16 hi/lo activation buffers (GEMM A operands)
__device__ __nv_bfloat16 g_inh [NPIX * CC], g_inl [NPIX * CC];
__device__ __nv_bfloat16 g_x1h [NPIX * CC], g_x1l [NPIX * CC];
__device__ __nv_bfloat16 g_smh [NPIX * CC], g_sml [NPIX * CC];

// Pre-split, pre-transposed weights: [n][k] bf16 hi/lo
__device__ __nv_bfloat16 g_wTin_h [CC * CC], g_wTin_l [CC * CC];
__device__ __nv_bfloat16 g_wTom_h [CC * CC], g_wTom_l [CC * CC]; // off|mask|zero
__device__ __nv_bfloat16 g_wTout_h[CC * CC], g_wTout_l[CC * CC];
__device__ float g_bom[CC];

// ---------------------------------------------------------------------------
// split helpers
// ---------------------------------------------------------------------------
__device__ __forceinline__ void split4(float4 v, uint2& hi, uint2& lo) {
    __nv_bfloat162 h01 = __floats2bfloat162_rn(v.x, v.y);
    __nv_bfloat162 h23 = __floats2bfloat162_rn(v.z, v.w);
    float2 f01 = __bfloat1622float2(h01);
    float2 f23 = __bfloat1622float2(h23);
    __nv_bfloat162 l01 = __floats2bfloat162_rn(v.x - f01.x, v.y - f01.y);
    __nv_bfloat162 l23 = __floats2bfloat162_rn(v.z - f23.x, v.w - f23.y);
    hi.x = reinterpret_cast<unsigned&>(h01); hi.y = reinterpret_cast<unsigned&>(h23);
    lo.x = reinterpret_cast<unsigned&>(l01); lo.y = reinterpret_cast<unsigned&>(l23);
}

// ---------------------------------------------------------------------------
// Weight prep: transpose + bf16 split. grid(256, 3), block 256 (tid = k).
// ---------------------------------------------------------------------------
__global__ void prep_weights(const float* __restrict__ w_in,
                             const float* __restrict__ w_off,
                             const float* __restrict__ w_mask,
                             const float* __restrict__ w_out,
                             const float* __restrict__ b_off,
                             const float* __restrict__ b_mask) {
    int n = blockIdx.x, mat = blockIdx.y, k = threadIdx.x;
    float v;
    __nv_bfloat16 *dh, *dl;
    if (mat == 0)      { v = w_in [k * 256 + n]; dh = g_wTin_h;  dl = g_wTin_l; }
    else if (mat == 2) { v = w_out[k * 256 + n]; dh = g_wTout_h; dl = g_wTout_l; }
    else {
        if (n < 144)      v = w_off [k * 144 + n];
        else if (n < 216) v = w_mask[k * 72 + (n - 144)];
        else              v = 0.f;
        dh = g_wTom_h; dl = g_wTom_l;
        if (n == 0)
            g_bom[k] = (k < 144) ? b_off[k] : (k < 216 ? b_mask[k - 144] : 0.f);
    }
    __nv_bfloat16 h = __float2bfloat16_rn(v);
    __nv_bfloat16 l = __float2bfloat16_rn(v - __bfloat162float(h));
    dh[n * 256 + k] = h;
    dl[n * 256 + k] = l;
}

// ---------------------------------------------------------------------------
// Convert external inputs -> bf16 hi/lo  (thread = one float4)
// ---------------------------------------------------------------------------
__global__ void convert_inputs(const float* __restrict__ in) {
    int i = blockIdx.x * blockDim.x + threadIdx.x;
    if (i >= NPIX * CC / 4) return;
    float4 v = ((const float4*)in)[i];
    uint2 hi, lo;
    split4(v, hi, lo);
    ((uint2*)g_inh)[i] = hi;
    ((uint2*)g_inl)[i] = lo;
}

// ---------------------------------------------------------------------------
// Zero the 1-pixel ring of the padded buffer
// ---------------------------------------------------------------------------
__global__ void zero_ring_kernel() {
    int idx = blockIdx.x * blockDim.x + threadIdx.x;
    const int total = BATCH * 260 * 64;
    if (idx >= total) return;
    int p = idx >> 6, c4 = idx & 63;
    int b = p / 260, r = p % 260;
    int h, w;
    if (r < 66)       { h = 0;       w = r; }
    else if (r < 132) { h = 65;      w = r - 66; }
    else if (r < 196) { h = r - 131; w = 0; }
    else              { h = r - 195; w = 65; }
    size_t a = (((size_t)(b * HP + h) * WP + w) * CC) + c4 * 4;
    *(float4*)(g_xpad + a) = make_float4(0.f, 0.f, 0.f, 0.f);
}

// ---------------------------------------------------------------------------
// MMA / ldmatrix / cp.async helpers
// ---------------------------------------------------------------------------
#define MMA_BF16(d, a, b)                                                      \
    asm volatile("mma.sync.aligned.m16n8k16.row.col.f32.bf16.bf16.f32 "        \
        "{%0,%1,%2,%3}, {%4,%5,%6,%7}, {%8,%9}, {%0,%1,%2,%3};"                \
        : "+f"((d)[0]), "+f"((d)[1]), "+f"((d)[2]), "+f"((d)[3])               \
        : "r"((a)[0]), "r"((a)[1]), "r"((a)[2]), "r"((a)[3]),                  \
          "r"((b)[0]), "r"((b)[1]))

__device__ __forceinline__ void ldsm4(unsigned* r, uint32_t addr) {
    asm volatile("ldmatrix.sync.aligned.m8n8.x4.shared.b16 {%0,%1,%2,%3}, [%4];"
        : "=r"(r[0]), "=r"(r[1]), "=r"(r[2]), "=r"(r[3]) : "r"(addr));
}

__device__ __forceinline__ void cp16(uint32_t s, const void* g) {
    asm volatile("cp.async.cg.shared.global [%0], [%1], 16;" :: "r"(s), "l"(g));
}
__device__ __forceinline__ void cp_commit() {
    asm volatile("cp.async.commit_group;");
}
template<int N>
__device__ __forceinline__ void cp_wait() {
    asm volatile("cp.async.wait_group %0;" :: "n"(N));
}

// Swizzled smem offset for (row, chunk) with 32B rows, 2 chunks of 16B:
// physical slot = chunk ^ ((row>>2)&1). All addresses multiples of 16.
__device__ __forceinline__ uint32_t sw_off(int row, int chunk) {
    return (uint32_t)(row * 32 + ((chunk ^ ((row >> 2) & 1)) << 4));
}

// ---------------------------------------------------------------------------
// bf16 split-precision tensor-core GEMM, cp.async 3-stage pipeline.
// C[M,N] = A[M,256] @ B[256,N] + bias
// BM=128, BN=64, BK=16, 256 threads (8 warps 4x2), warp tile 32x32.
// SMEM: 32-byte rows (16 bf16), XOR-swizzled chunks -> conflict-free ldmatrix
// and conflict-free cp.async stores; all addresses 16B-aligned by construction.
// Stage: Ah 4096 + Al 4096 + Bh 2048 + Bl 2048 = 12288B; 3 stages = 36864B.
// SRC:  0 g_in, 1 g_x1, 2 g_sm
// DST:  0 ext, 1 g_xpad (padded layout), 2 fused off|mask split
// WSEL: 0 w_in, 1 off|mask (bias g_bom), 2 w_out
// ---------------------------------------------------------------------------
#define BK     16
#define ST_AH  0
#define ST_AL  4096
#define ST_BH  8192
#define ST_BL  10240
#define ST_SZ  12288
#define NSTAGE 3

template<int SRC, int DST, int WSEL>
__global__ __launch_bounds__(256)
void sgemm_bf16(const float* __restrict__ bias_ext,
                float* __restrict__ Cext,
                int N) {
    const __nv_bfloat16* __restrict__ Agh =
        (SRC == 0) ? g_inh : (SRC == 1) ? g_x1h : g_smh;
    const __nv_bfloat16* __restrict__ Agl =
        (SRC == 0) ? g_inl : (SRC == 1) ? g_x1l : g_sml;
    const __nv_bfloat16* __restrict__ BTh =
        (WSEL == 0) ? g_wTin_h : (WSEL == 1) ? g_wTom_h : g_wTout_h;
    const __nv_bfloat16* __restrict__ BTl =
        (WSEL == 0) ? g_wTin_l : (WSEL == 1) ? g_wTom_l : g_wTout_l;
    const float* __restrict__ bias = (WSEL == 1) ? (const float*)g_bom : bias_ext;

    __shared__ __align__(128) char smem[NSTAGE * ST_SZ];
    const uint32_t s_base = (uint32_t)__cvta_generic_to_shared(smem);

    const int tid  = threadIdx.x;
    const int warp = tid >> 5;
    const int lane = tid & 31;
    const int wm = warp >> 1;   // 0..3 (32-row slice of 128)
    const int wn = warp & 1;    // 0..1 (32-col slice of 64)
    const int brow = blockIdx.y * 128;
    const int bcol = blockIdx.x * 64;

    float d[2][4][4];
#pragma unroll
    for (int i = 0; i < 2; i++)
#pragma unroll
        for (int j = 0; j < 4; j++)
#pragma unroll
            for (int k = 0; k < 4; k++) d[i][j][k] = 0.f;

    // cp.async mapping (3 x 16B per thread per stage):
    // A: row tid>>1, chunk tid&1 — one hi + one lo per thread (512 chunks).
    // B: tid<128 -> hi buffer, else lo; row (tid&127)>>1, chunk tid&1.
    const int arow = tid >> 1;
    const int ac   = tid & 1;
    const int bhalf = tid >> 7;
    const int brw2  = (tid & 127) >> 1;
    const int bc    = tid & 1;

    auto ldgsts = [&](int kidx, int st) {
        int k0 = kidx * BK;
        uint32_t sb = s_base + st * ST_SZ;
        uint32_t dsA = sw_off(arow, ac);
        cp16(sb + ST_AH + dsA, Agh + (size_t)(brow + arow) * 256 + k0 + ac * 8);
        cp16(sb + ST_AL + dsA, Agl + (size_t)(brow + arow) * 256 + k0 + ac * 8);
        uint32_t dsB = sw_off(brw2, bc);
        const __nv_bfloat16* bp =
            (bhalf ? BTl : BTh) + (size_t)(bcol + brw2) * 256 + k0 + bc * 8;
        cp16(sb + (bhalf ? ST_BL : ST_BH) + dsB, bp);
    };

    const int t  = lane >> 3;
    const int lr = lane & 7;

    auto compute = [&](int st) {
        uint32_t sb = s_base + st * ST_SZ;
        unsigned ahf[2][4], alf[2][4], bhf[4][2], blf[4][2];
#pragma unroll
        for (int ms = 0; ms < 2; ms++) {
            int row = wm * 32 + ms * 16 + ((t & 1) << 3) + lr;
            uint32_t aoff = sw_off(row, t >> 1);
            ldsm4(ahf[ms], sb + ST_AH + aoff);
            ldsm4(alf[ms], sb + ST_AL + aoff);
        }
#pragma unroll
        for (int nb = 0; nb < 2; nb++) {
            int row = wn * 32 + nb * 16 + ((t >> 1) << 3) + lr;
            uint32_t boff = sw_off(row, t & 1);
            unsigned rh[4], rl[4];
            ldsm4(rh, sb + ST_BH + boff);
            ldsm4(rl, sb + ST_BL + boff);
            bhf[nb * 2 + 0][0] = rh[0]; bhf[nb * 2 + 0][1] = rh[1];
            bhf[nb * 2 + 1][0] = rh[2]; bhf[nb * 2 + 1][1] = rh[3];
            blf[nb * 2 + 0][0] = rl[0]; blf[nb * 2 + 0][1] = rl[1];
            blf[nb * 2 + 1][0] = rl[2]; blf[nb * 2 + 1][1] = rl[3];
        }
#pragma unroll
        for (int ms = 0; ms < 2; ms++)
#pragma unroll
            for (int ns = 0; ns < 4; ns++) {
                MMA_BF16(d[ms][ns], ahf[ms], bhf[ns]);
                MMA_BF16(d[ms][ns], ahf[ms], blf[ns]);
                MMA_BF16(d[ms][ns], alf[ms], bhf[ns]);
            }
    };

    // pipeline: 16 k-iterations, 3 stages
    ldgsts(0, 0); cp_commit();
    ldgsts(1, 1); cp_commit();
    ldgsts(2, 2); cp_commit();
    cp_wait<2>();
    __syncthreads();
    int cs = 0;
    for (int it = 0; it < 16; it++) {
        compute(cs);
        __syncthreads();
        if (it + 3 < 16) {
            ldgsts(it + 3, cs); cp_commit();
            cp_wait<2>();
        } else {
            cp_wait<0>();
        }
        __syncthreads();
        cs = (cs == 2) ? 0 : cs + 1;
    }

    // epilogue
#pragma unroll
    for (int ms = 0; ms < 2; ms++) {
        int row0 = brow + wm * 32 + ms * 16 + (lane >> 2);
#pragma unroll
        for (int half = 0; half < 2; half++) {
            int row = row0 + half * 8;
#pragma unroll
            for (int ns = 0; ns < 4; ns++) {
                int col = bcol + wn * 32 + ns * 8 + 2 * (lane & 3);
                if (col >= N) continue;
                float2 v;
                v.x = d[ms][ns][half * 2 + 0] + bias[col];
                v.y = d[ms][ns][half * 2 + 1] + bias[col + 1];
                if (DST == 1) {
                    int b = row >> 12, h = (row >> 6) & 63, w = row & 63;
                    size_t ob = ((size_t)(b * HP + h + 1) * WP + (w + 1)) * CC;
                    *(float2*)&g_xpad[ob + col] = v;
                } else if (DST == 2) {
                    if (col < 144)      *(float2*)&g_off [(size_t)row * 144 + col] = v;
                    else                *(float2*)&g_mask[(size_t)row * 72 + col - 144] = v;
                } else {
                    *(float2*)&Cext[(size_t)row * N + col] = v;
                }
            }
        }
    }
}

// ---------------------------------------------------------------------------
// Depthwise 3x3 + LayerNorm + exact GELU. Warp = 4 consecutive pixels.
// ---------------------------------------------------------------------------
__global__ __launch_bounds__(256)
void dwlngelu_kernel(const float* __restrict__ in,
                     const float* __restrict__ dwk,
                     const float* __restrict__ dwb,
                     const float* __restrict__ gamma,
                     const float* __restrict__ beta) {
    const int warp = threadIdx.x >> 5;
    const int lane = threadIdx.x & 31;
    const int pb = blockIdx.x * 32 + warp * 4;
    const int b = pb >> 12, h = (pb >> 6) & 63, w0 = pb & 63;
    const int c0 = lane * 4, c1 = 128 + lane * 4;

    float4 bias0 = *(const float4*)(dwb + c0);
    float4 bias1 = *(const float4*)(dwb + c1);
    float4 a0[4], a1[4];
#pragma unroll
    for (int i = 0; i < 4; i++) { a0[i] = bias0; a1[i] = bias1; }

#pragma unroll
    for (int ky = 0; ky < 3; ky++) {
        int hh = h + ky - 1;
        if (hh < 0 || hh >= HH) continue;
        float4 kw0[3], kw1[3];
#pragma unroll
        for (int kx = 0; kx < 3; kx++) {
            kw0[kx] = *(const float4*)(dwk + (ky * 3 + kx) * CC + c0);
            kw1[kx] = *(const float4*)(dwk + (ky * 3 + kx) * CC + c1);
        }
        const float* row = in + (size_t)(b * HH + hh) * WW * CC;
#pragma unroll
        for (int j = 0; j < 6; j++) {
            int ww = w0 - 1 + j;
            if (ww < 0 || ww >= WW) continue;
            float4 x0 = *(const float4*)(row + (size_t)ww * CC + c0);
            float4 x1 = *(const float4*)(row + (size_t)ww * CC + c1);
#pragma unroll
            for (int i = 0; i < 4; i++) {
                int kx = j - i;
                if (kx < 0 || kx > 2) continue;
                a0[i].x += x0.x * kw0[kx].x; a0[i].y += x0.y * kw0[kx].y;
                a0[i].z += x0.z * kw0[kx].z; a0[i].w += x0.w * kw0[kx].w;
                a1[i].x += x1.x * kw1[kx].x; a1[i].y += x1.y * kw1[kx].y;
                a1[i].z += x1.z * kw1[kx].z; a1[i].w += x1.w * kw1[kx].w;
            }
        }
    }

    float4 ga0 = *(const float4*)(gamma + c0), ga1 = *(const float4*)(gamma + c1);
    float4 be0 = *(const float4*)(beta + c0),  be1 = *(const float4*)(beta + c1);

#pragma unroll
    for (int i = 0; i < 4; i++) {
        float4 s0 = a0[i], s1 = a1[i];
        float sum = s0.x + s0.y + s0.z + s0.w + s1.x + s1.y + s1.z + s1.w;
        float sq  = s0.x*s0.x + s0.y*s0.y + s0.z*s0.z + s0.w*s0.w
                  + s1.x*s1.x + s1.y*s1.y + s1.z*s1.z + s1.w*s1.w;
#pragma unroll
        for (int off = 16; off > 0; off >>= 1) {
            sum += __shfl_xor_sync(0xFFFFFFFFu, sum, off);
            sq  += __shfl_xor_sync(0xFFFFFFFFu, sq,  off);
        }
        float mu  = sum * (1.0f / 256.0f);
        float var = sq * (1.0f / 256.0f) - mu * mu;
        float rstd = rsqrtf(var + 1e-6f);

        float4 r0, r1;
        float y;
        y = (s0.x - mu) * rstd * ga0.x + be0.x; r0.x = 0.5f * y * (1.f + erff(y * 0.70710678118654752f));
        y = (s0.y - mu) * rstd * ga0.y + be0.y; r0.y = 0.5f * y * (1.f + erff(y * 0.70710678118654752f));
        y = (s0.z - mu) * rstd * ga0.z + be0.z; r0.z = 0.5f * y * (1.f + erff(y * 0.70710678118654752f));
        y = (s0.w - mu) * rstd * ga0.w + be0.w; r0.w = 0.5f * y * (1.f + erff(y * 0.70710678118654752f));
        y = (s1.x - mu) * rstd * ga1.x + be1.x; r1.x = 0.5f * y * (1.f + erff(y * 0.70710678118654752f));
        y = (s1.y - mu) * rstd * ga1.y + be1.y; r1.y = 0.5f * y * (1.f + erff(y * 0.70710678118654752f));
        y = (s1.z - mu) * rstd * ga1.z + be1.z; r1.z = 0.5f * y * (1.f + erff(y * 0.70710678118654752f));
        y = (s1.w - mu) * rstd * ga1.w + be1.w; r1.w = 0.5f * y * (1.f + erff(y * 0.70710678118654752f));

        size_t ob = (size_t)(pb + i) * CC;
        uint2 h0, l0, h1, l1;
        split4(r0, h0, l0);
        split4(r1, h1, l1);
        *(uint2*)&g_x1h[ob + c0] = h0;  *(uint2*)&g_x1l[ob + c0] = l0;
        *(uint2*)&g_x1h[ob + c1] = h1;  *(uint2*)&g_x1l[ob + c1] = l1;
    }
}

// ---------------------------------------------------------------------------
// Deformable bilinear gather + inline softmax.
// Warp = (pixel, group). lane = (corner q, channel chunk cc).
// ---------------------------------------------------------------------------
__global__ __launch_bounds__(256)
void deform_sample_kernel() {
    const int p    = blockIdx.x * 8 + (threadIdx.x >> 5);
    const int g    = blockIdx.y;
    const int lane = threadIdx.x & 31;
    const int q    = lane >> 3;
    const int cc   = lane & 7;
    const int qx = q & 1, qy = q >> 1;
    const int b = p >> 12, h = (p >> 6) & 63, w = p & 63;

    const float* offp = g_off  + (size_t)p * 144 + g * 18;
    const float* mp   = g_mask + (size_t)p * 72  + g * 9;
    const float* base = g_xpad + (size_t)b * HP * WP * CC + g * GCH + cc * 4;

    float mk[K2], mx = -1e30f;
#pragma unroll
    for (int k = 0; k < K2; k++) { mk[k] = mp[k]; mx = fmaxf(mx, mk[k]); }
    float den = 0.f;
#pragma unroll
    for (int k = 0; k < K2; k++) { mk[k] = __expf(mk[k] - mx); den += mk[k]; }
    float inv = 1.0f / den;

    float4 acc = make_float4(0.f, 0.f, 0.f, 0.f);
#pragma unroll
    for (int k = 0; k < K2; k++) {
        float px = (float)(PADB + w) + (float)(k % 3 - 1) + offp[k * 2 + 0];
        float py = (float)(PADB + h) + (float)(k / 3 - 1) + offp[k * 2 + 1];
        float x0f = floorf(px), y0f = floorf(py);
        int xq = (int)x0f + qx, yq = (int)y0f + qy;
        float wx = px - x0f, wy = py - y0f;
        float wq = (qx ? wx : 1.f - wx) * (qy ? wy : 1.f - wy) * (mk[k] * inv);

        if (xq >= 0 && xq < WP && yq >= 0 && yq < HP) {
            float4 v = *(const float4*)(base + ((size_t)yq * WP + xq) * CC);
            acc.x += v.x * wq; acc.y += v.y * wq;
            acc.z += v.z * wq; acc.w += v.w * wq;
        }
    }
#pragma unroll
    for (int off = 8; off <= 16; off <<= 1) {
        acc.x += __shfl_xor_sync(0xFFFFFFFFu, acc.x, off);
        acc.y += __shfl_xor_sync(0xFFFFFFFFu, acc.y, off);
        acc.z += __shfl_xor_sync(0xFFFFFFFFu, acc.z, off);
        acc.w += __shfl_xor_sync(0xFFFFFFFFu, acc.w, off);
    }
    if (lane < 8) {
        uint2 hi, lo;
        split4(acc, hi, lo);
        size_t ob = (size_t)p * CC + g * GCH + cc * 4;
        *(uint2*)&g_smh[ob] = hi;
        *(uint2*)&g_sml[ob] = lo;
    }
}

// ---------------------------------------------------------------------------
// Launch (kernel launches only; NO device symbols referenced from host code)
// ---------------------------------------------------------------------------
extern "C" void kernel_launch(void* const* d_in, const int* in_sizes, int n_in,
                              void* d_out, int out_size) {
    const float* inputs   = (const float*)d_in[0];
    const float* w_in     = (const float*)d_in[1];
    const float* b_in     = (const float*)d_in[2];
    const float* dw_k     = (const float*)d_in[3];
    const float* dw_b     = (const float*)d_in[4];
    const float* ln_gamma = (const float*)d_in[5];
    const float* ln_beta  = (const float*)d_in[6];
    const float* w_off    = (const float*)d_in[7];
    const float* b_off    = (const float*)d_in[8];
    const float* w_mask   = (const float*)d_in[9];
    const float* b_mask   = (const float*)d_in[10];
    const float* w_out    = (const float*)d_in[11];
    const float* b_out    = (const float*)d_in[12];
    float* out = (float*)d_out;

    {
        dim3 grid(256, 3);
        prep_weights<<<grid, 256>>>(w_in, w_off, w_mask, w_out, b_off, b_mask);
    }
    convert_inputs<<<(NPIX * CC / 4 + 255) / 256, 256>>>(inputs);
    zero_ring_kernel<<<(BATCH * 260 * 64 + 255) / 256, 256>>>();
    {
        dim3 grid(CC / 64, NPIX / 128);
        sgemm_bf16<0, 1, 0><<<grid, 256>>>(b_in, nullptr, CC);
    }
    dwlngelu_kernel<<<NPIX / 32, 256>>>(inputs, dw_k, dw_b, ln_gamma, ln_beta);
    {
        dim3 grid(256 / 64, NPIX / 128);
        sgemm_bf16<1, 2, 1><<<grid, 256>>>(nullptr, nullptr, 216);
    }
    {
        dim3 grid(NPIX / 8, GG);
        deform_sample_kernel<<<grid, 256>>>();
    }
    {
        dim3 grid(CC / 64, NPIX / 128);
        sgemm_bf16<2, 0, 2><<<grid, 256>>>(b_out, out, CC);
    }
    (void)in_sizes; (void)n_in; (void)out_size;
}

// round 14
// speedup vs baseline: 2.0814x; 1.0034x over previous
#include <cuda_runtime.h>
#include <cuda_bf16.h>
#include <math.h>
#include <stdint.h>

// ---------------------------------------------------------------------------
// Problem constants
// ---------------------------------------------------------------------------
#define BATCH 8
#define HH    64
#define WW    64
#define CC    256
#define GG    8
#define GCH   32
#define K2    9
#define PADB  1
#define HP    66
#define WP    66
#define NPIX  (BATCH*HH*WW) // 32768

// ---------------------------------------------------------------------------
// Scratch (device globals) — referenced ONLY from device code.
// ---------------------------------------------------------------------------
__device__ float g_xpad[BATCH * HP * WP * CC];       // padded x_proj (fp32)
__device__ float g_off [NPIX * 144];                 // offsets
__device__ float g_mask[NPIX * 72];                  // mask logits (softmax in sampler)

// bf16 hi/lo activation buffers (GEMM A operands)
__device__ __nv_bfloat16 g_inh [NPIX * CC], g_inl [NPIX * CC];
__device__ __nv_bfloat16 g_x1h [NPIX * CC], g_x1l [NPIX * CC];
__device__ __nv_bfloat16 g_smh [NPIX * CC], g_sml [NPIX * CC];

// Pre-split, pre-transposed weights: [n][k] bf16 hi/lo
__device__ __nv_bfloat16 g_wTin_h [CC * CC], g_wTin_l [CC * CC];
__device__ __nv_bfloat16 g_wTom_h [CC * CC], g_wTom_l [CC * CC]; // off|mask|zero
__device__ __nv_bfloat16 g_wTout_h[CC * CC], g_wTout_l[CC * CC];
__device__ float g_bom[CC];

// ---------------------------------------------------------------------------
// split helpers
// ---------------------------------------------------------------------------
__device__ __forceinline__ void split4(float4 v, uint2& hi, uint2& lo) {
    __nv_bfloat162 h01 = __floats2bfloat162_rn(v.x, v.y);
    __nv_bfloat162 h23 = __floats2bfloat162_rn(v.z, v.w);
    float2 f01 = __bfloat1622float2(h01);
    float2 f23 = __bfloat1622float2(h23);
    __nv_bfloat162 l01 = __floats2bfloat162_rn(v.x - f01.x, v.y - f01.y);
    __nv_bfloat162 l23 = __floats2bfloat162_rn(v.z - f23.x, v.w - f23.y);
    hi.x = reinterpret_cast<unsigned&>(h01); hi.y = reinterpret_cast<unsigned&>(h23);
    lo.x = reinterpret_cast<unsigned&>(l01); lo.y = reinterpret_cast<unsigned&>(l23);
}

// ---------------------------------------------------------------------------
// Weight prep: transpose + bf16 split. grid(256, 3), block 256 (tid = k).
// ---------------------------------------------------------------------------
__global__ void prep_weights(const float* __restrict__ w_in,
                             const float* __restrict__ w_off,
                             const float* __restrict__ w_mask,
                             const float* __restrict__ w_out,
                             const float* __restrict__ b_off,
                             const float* __restrict__ b_mask) {
    int n = blockIdx.x, mat = blockIdx.y, k = threadIdx.x;
    float v;
    __nv_bfloat16 *dh, *dl;
    if (mat == 0)      { v = w_in [k * 256 + n]; dh = g_wTin_h;  dl = g_wTin_l; }
    else if (mat == 2) { v = w_out[k * 256 + n]; dh = g_wTout_h; dl = g_wTout_l; }
    else {
        if (n < 144)      v = w_off [k * 144 + n];
        else if (n < 216) v = w_mask[k * 72 + (n - 144)];
        else              v = 0.f;
        dh = g_wTom_h; dl = g_wTom_l;
        if (n == 0)
            g_bom[k] = (k < 144) ? b_off[k] : (k < 216 ? b_mask[k - 144] : 0.f);
    }
    __nv_bfloat16 h = __float2bfloat16_rn(v);
    __nv_bfloat16 l = __float2bfloat16_rn(v - __bfloat162float(h));
    dh[n * 256 + k] = h;
    dl[n * 256 + k] = l;
}

// ---------------------------------------------------------------------------
// Convert external inputs -> bf16 hi/lo  (thread = one float4)
// ---------------------------------------------------------------------------
__global__ void convert_inputs(const float* __restrict__ in) {
    int i = blockIdx.x * blockDim.x + threadIdx.x;
    if (i >= NPIX * CC / 4) return;
    float4 v = ((const float4*)in)[i];
    uint2 hi, lo;
    split4(v, hi, lo);
    ((uint2*)g_inh)[i] = hi;
    ((uint2*)g_inl)[i] = lo;
}

// ---------------------------------------------------------------------------
// Zero the 1-pixel ring of the padded buffer
// ---------------------------------------------------------------------------
__global__ void zero_ring_kernel() {
    int idx = blockIdx.x * blockDim.x + threadIdx.x;
    const int total = BATCH * 260 * 64;
    if (idx >= total) return;
    int p = idx >> 6, c4 = idx & 63;
    int b = p / 260, r = p % 260;
    int h, w;
    if (r < 66)       { h = 0;       w = r; }
    else if (r < 132) { h = 65;      w = r - 66; }
    else if (r < 196) { h = r - 131; w = 0; }
    else              { h = r - 195; w = 65; }
    size_t a = (((size_t)(b * HP + h) * WP + w) * CC) + c4 * 4;
    *(float4*)(g_xpad + a) = make_float4(0.f, 0.f, 0.f, 0.f);
}

// ---------------------------------------------------------------------------
// MMA / ldmatrix / cp.async helpers
// ---------------------------------------------------------------------------
#define MMA_BF16(d, a, b)                                                      \
    asm volatile("mma.sync.aligned.m16n8k16.row.col.f32.bf16.bf16.f32 "        \
        "{%0,%1,%2,%3}, {%4,%5,%6,%7}, {%8,%9}, {%0,%1,%2,%3};"                \
        : "+f"((d)[0]), "+f"((d)[1]), "+f"((d)[2]), "+f"((d)[3])               \
        : "r"((a)[0]), "r"((a)[1]), "r"((a)[2]), "r"((a)[3]),                  \
          "r"((b)[0]), "r"((b)[1]))

__device__ __forceinline__ void ldsm4(unsigned* r, uint32_t addr) {
    asm volatile("ldmatrix.sync.aligned.m8n8.x4.shared.b16 {%0,%1,%2,%3}, [%4];"
        : "=r"(r[0]), "=r"(r[1]), "=r"(r[2]), "=r"(r[3]) : "r"(addr));
}

__device__ __forceinline__ void cp16(uint32_t s, const void* g) {
    asm volatile("cp.async.cg.shared.global [%0], [%1], 16;" :: "r"(s), "l"(g));
}
__device__ __forceinline__ void cp_commit() {
    asm volatile("cp.async.commit_group;");
}
template<int N>
__device__ __forceinline__ void cp_wait() {
    asm volatile("cp.async.wait_group %0;" :: "n"(N));
}

// Swizzled smem offset for (row, chunk) with 32B rows, 2 chunks of 16B:
// physical slot = chunk ^ ((row>>2)&1). All addresses multiples of 16.
__device__ __forceinline__ uint32_t sw_off(int row, int chunk) {
    return (uint32_t)(row * 32 + ((chunk ^ ((row >> 2) & 1)) << 4));
}

// ---------------------------------------------------------------------------
// bf16 split-precision tensor-core GEMM, cp.async 3-stage pipeline,
// ONE __syncthreads per k-iteration (load issued after the barrier into the
// slot computed last iteration; barrier proves all warps finished reading it).
// C[M,N] = A[M,256] @ B[256,N] + bias
// BM=128, BN=64, BK=16, 256 threads (8 warps 4x2), warp tile 32x32.
// SMEM: 32B rows, XOR-swizzled 16B chunks; 3 stages x 12288B = 36864B.
// SRC:  0 g_in, 1 g_x1, 2 g_sm
// DST:  0 ext, 1 g_xpad (padded layout), 2 fused off|mask split
// WSEL: 0 w_in, 1 off|mask (bias g_bom), 2 w_out
// ---------------------------------------------------------------------------
#define BK     16
#define ST_AH  0
#define ST_AL  4096
#define ST_BH  8192
#define ST_BL  10240
#define ST_SZ  12288
#define NSTAGE 3

template<int SRC, int DST, int WSEL>
__global__ __launch_bounds__(256)
void sgemm_bf16(const float* __restrict__ bias_ext,
                float* __restrict__ Cext,
                int N) {
    const __nv_bfloat16* __restrict__ Agh =
        (SRC == 0) ? g_inh : (SRC == 1) ? g_x1h : g_smh;
    const __nv_bfloat16* __restrict__ Agl =
        (SRC == 0) ? g_inl : (SRC == 1) ? g_x1l : g_sml;
    const __nv_bfloat16* __restrict__ BTh =
        (WSEL == 0) ? g_wTin_h : (WSEL == 1) ? g_wTom_h : g_wTout_h;
    const __nv_bfloat16* __restrict__ BTl =
        (WSEL == 0) ? g_wTin_l : (WSEL == 1) ? g_wTom_l : g_wTout_l;
    const float* __restrict__ bias = (WSEL == 1) ? (const float*)g_bom : bias_ext;

    __shared__ __align__(128) char smem[NSTAGE * ST_SZ];
    const uint32_t s_base = (uint32_t)__cvta_generic_to_shared(smem);

    const int tid  = threadIdx.x;
    const int warp = tid >> 5;
    const int lane = tid & 31;
    const int wm = warp >> 1;   // 0..3 (32-row slice of 128)
    const int wn = warp & 1;    // 0..1 (32-col slice of 64)
    const int brow = blockIdx.y * 128;
    const int bcol = blockIdx.x * 64;

    float d[2][4][4];
#pragma unroll
    for (int i = 0; i < 2; i++)
#pragma unroll
        for (int j = 0; j < 4; j++)
#pragma unroll
            for (int k = 0; k < 4; k++) d[i][j][k] = 0.f;

    // cp.async mapping (3 x 16B per thread per stage):
    // A: row tid>>1, chunk tid&1 — one hi + one lo per thread (512 chunks).
    // B: tid<128 -> hi buffer, else lo; row (tid&127)>>1, chunk tid&1.
    const int arow = tid >> 1;
    const int ac   = tid & 1;
    const int bhalf = tid >> 7;
    const int brw2  = (tid & 127) >> 1;
    const int bc    = tid & 1;

    auto ldgsts = [&](int kidx, int st) {
        int k0 = kidx * BK;
        uint32_t sb = s_base + st * ST_SZ;
        uint32_t dsA = sw_off(arow, ac);
        cp16(sb + ST_AH + dsA, Agh + (size_t)(brow + arow) * 256 + k0 + ac * 8);
        cp16(sb + ST_AL + dsA, Agl + (size_t)(brow + arow) * 256 + k0 + ac * 8);
        uint32_t dsB = sw_off(brw2, bc);
        const __nv_bfloat16* bp =
            (bhalf ? BTl : BTh) + (size_t)(bcol + brw2) * 256 + k0 + bc * 8;
        cp16(sb + (bhalf ? ST_BL : ST_BH) + dsB, bp);
    };

    const int t  = lane >> 3;
    const int lr = lane & 7;

    auto compute = [&](int st) {
        uint32_t sb = s_base + st * ST_SZ;
        unsigned ahf[2][4], alf[2][4], bhf[4][2], blf[4][2];
#pragma unroll
        for (int ms = 0; ms < 2; ms++) {
            int row = wm * 32 + ms * 16 + ((t & 1) << 3) + lr;
            uint32_t aoff = sw_off(row, t >> 1);
            ldsm4(ahf[ms], sb + ST_AH + aoff);
            ldsm4(alf[ms], sb + ST_AL + aoff);
        }
#pragma unroll
        for (int nb = 0; nb < 2; nb++) {
            int row = wn * 32 + nb * 16 + ((t >> 1) << 3) + lr;
            uint32_t boff = sw_off(row, t & 1);
            unsigned rh[4], rl[4];
            ldsm4(rh, sb + ST_BH + boff);
            ldsm4(rl, sb + ST_BL + boff);
            bhf[nb * 2 + 0][0] = rh[0]; bhf[nb * 2 + 0][1] = rh[1];
            bhf[nb * 2 + 1][0] = rh[2]; bhf[nb * 2 + 1][1] = rh[3];
            blf[nb * 2 + 0][0] = rl[0]; blf[nb * 2 + 0][1] = rl[1];
            blf[nb * 2 + 1][0] = rl[2]; blf[nb * 2 + 1][1] = rl[3];
        }
#pragma unroll
        for (int ms = 0; ms < 2; ms++)
#pragma unroll
            for (int ns = 0; ns < 4; ns++) {
                MMA_BF16(d[ms][ns], ahf[ms], bhf[ns]);
                MMA_BF16(d[ms][ns], ahf[ms], blf[ns]);
                MMA_BF16(d[ms][ns], alf[ms], bhf[ns]);
            }
    };

    // pipeline: 16 k-iterations, 3 stages, ONE barrier per iteration.
    // Prologue loads stages 0,1. At iter it: wait(stage it) -> barrier ->
    // load stage it+2 into the slot computed at it-1 -> compute stage it.
    ldgsts(0, 0); cp_commit();
    ldgsts(1, 1); cp_commit();
    int cs = 0;            // slot holding stage it
    int ws = 2;            // slot to write stage it+2 into
    for (int it = 0; it < 16; it++) {
        if (it + 2 < 16) cp_wait<1>(); else cp_wait<0>();
        __syncthreads();
        if (it + 2 < 16) { ldgsts(it + 2, ws); cp_commit(); }
        compute(cs);
        ws = cs;
        cs = (cs == 2) ? 0 : cs + 1;
    }

    // epilogue
#pragma unroll
    for (int ms = 0; ms < 2; ms++) {
        int row0 = brow + wm * 32 + ms * 16 + (lane >> 2);
#pragma unroll
        for (int half = 0; half < 2; half++) {
            int row = row0 + half * 8;
#pragma unroll
            for (int ns = 0; ns < 4; ns++) {
                int col = bcol + wn * 32 + ns * 8 + 2 * (lane & 3);
                if (col >= N) continue;
                float2 v;
                v.x = d[ms][ns][half * 2 + 0] + bias[col];
                v.y = d[ms][ns][half * 2 + 1] + bias[col + 1];
                if (DST == 1) {
                    int b = row >> 12, h = (row >> 6) & 63, w = row & 63;
                    size_t ob = ((size_t)(b * HP + h + 1) * WP + (w + 1)) * CC;
                    *(float2*)&g_xpad[ob + col] = v;
                } else if (DST == 2) {
                    if (col < 144)      *(float2*)&g_off [(size_t)row * 144 + col] = v;
                    else                *(float2*)&g_mask[(size_t)row * 72 + col - 144] = v;
                } else {
                    *(float2*)&Cext[(size_t)row * N + col] = v;
                }
            }
        }
    }
}

// ---------------------------------------------------------------------------
// Depthwise 3x3 + LayerNorm + exact GELU. Warp = 4 consecutive pixels.
// ---------------------------------------------------------------------------
__global__ __launch_bounds__(256)
void dwlngelu_kernel(const float* __restrict__ in,
                     const float* __restrict__ dwk,
                     const float* __restrict__ dwb,
                     const float* __restrict__ gamma,
                     const float* __restrict__ beta) {
    const int warp = threadIdx.x >> 5;
    const int lane = threadIdx.x & 31;
    const int pb = blockIdx.x * 32 + warp * 4;
    const int b = pb >> 12, h = (pb >> 6) & 63, w0 = pb & 63;
    const int c0 = lane * 4, c1 = 128 + lane * 4;

    float4 bias0 = *(const float4*)(dwb + c0);
    float4 bias1 = *(const float4*)(dwb + c1);
    float4 a0[4], a1[4];
#pragma unroll
    for (int i = 0; i < 4; i++) { a0[i] = bias0; a1[i] = bias1; }

#pragma unroll
    for (int ky = 0; ky < 3; ky++) {
        int hh = h + ky - 1;
        if (hh < 0 || hh >= HH) continue;
        float4 kw0[3], kw1[3];
#pragma unroll
        for (int kx = 0; kx < 3; kx++) {
            kw0[kx] = *(const float4*)(dwk + (ky * 3 + kx) * CC + c0);
            kw1[kx] = *(const float4*)(dwk + (ky * 3 + kx) * CC + c1);
        }
        const float* row = in + (size_t)(b * HH + hh) * WW * CC;
#pragma unroll
        for (int j = 0; j < 6; j++) {
            int ww = w0 - 1 + j;
            if (ww < 0 || ww >= WW) continue;
            float4 x0 = *(const float4*)(row + (size_t)ww * CC + c0);
            float4 x1 = *(const float4*)(row + (size_t)ww * CC + c1);
#pragma unroll
            for (int i = 0; i < 4; i++) {
                int kx = j - i;
                if (kx < 0 || kx > 2) continue;
                a0[i].x += x0.x * kw0[kx].x; a0[i].y += x0.y * kw0[kx].y;
                a0[i].z += x0.z * kw0[kx].z; a0[i].w += x0.w * kw0[kx].w;
                a1[i].x += x1.x * kw1[kx].x; a1[i].y += x1.y * kw1[kx].y;
                a1[i].z += x1.z * kw1[kx].z; a1[i].w += x1.w * kw1[kx].w;
            }
        }
    }

    float4 ga0 = *(const float4*)(gamma + c0), ga1 = *(const float4*)(gamma + c1);
    float4 be0 = *(const float4*)(beta + c0),  be1 = *(const float4*)(beta + c1);

#pragma unroll
    for (int i = 0; i < 4; i++) {
        float4 s0 = a0[i], s1 = a1[i];
        float sum = s0.x + s0.y + s0.z + s0.w + s1.x + s1.y + s1.z + s1.w;
        float sq  = s0.x*s0.x + s0.y*s0.y + s0.z*s0.z + s0.w*s0.w
                  + s1.x*s1.x + s1.y*s1.y + s1.z*s1.z + s1.w*s1.w;
#pragma unroll
        for (int off = 16; off > 0; off >>= 1) {
            sum += __shfl_xor_sync(0xFFFFFFFFu, sum, off);
            sq  += __shfl_xor_sync(0xFFFFFFFFu, sq,  off);
        }
        float mu  = sum * (1.0f / 256.0f);
        float var = sq * (1.0f / 256.0f) - mu * mu;
        float rstd = rsqrtf(var + 1e-6f);

        float4 r0, r1;
        float y;
        y = (s0.x - mu) * rstd * ga0.x + be0.x; r0.x = 0.5f * y * (1.f + erff(y * 0.70710678118654752f));
        y = (s0.y - mu) * rstd * ga0.y + be0.y; r0.y = 0.5f * y * (1.f + erff(y * 0.70710678118654752f));
        y = (s0.z - mu) * rstd * ga0.z + be0.z; r0.z = 0.5f * y * (1.f + erff(y * 0.70710678118654752f));
        y = (s0.w - mu) * rstd * ga0.w + be0.w; r0.w = 0.5f * y * (1.f + erff(y * 0.70710678118654752f));
        y = (s1.x - mu) * rstd * ga1.x + be1.x; r1.x = 0.5f * y * (1.f + erff(y * 0.70710678118654752f));
        y = (s1.y - mu) * rstd * ga1.y + be1.y; r1.y = 0.5f * y * (1.f + erff(y * 0.70710678118654752f));
        y = (s1.z - mu) * rstd * ga1.z + be1.z; r1.z = 0.5f * y * (1.f + erff(y * 0.70710678118654752f));
        y = (s1.w - mu) * rstd * ga1.w + be1.w; r1.w = 0.5f * y * (1.f + erff(y * 0.70710678118654752f));

        size_t ob = (size_t)(pb + i) * CC;
        uint2 h0, l0, h1, l1;
        split4(r0, h0, l0);
        split4(r1, h1, l1);
        *(uint2*)&g_x1h[ob + c0] = h0;  *(uint2*)&g_x1l[ob + c0] = l0;
        *(uint2*)&g_x1h[ob + c1] = h1;  *(uint2*)&g_x1l[ob + c1] = l1;
    }
}

// ---------------------------------------------------------------------------
// Deformable bilinear gather + inline softmax.
// Warp = (pixel, group). lane = (corner q, channel chunk cc).
// ---------------------------------------------------------------------------
__global__ __launch_bounds__(256)
void deform_sample_kernel() {
    const int p    = blockIdx.x * 8 + (threadIdx.x >> 5);
    const int g    = blockIdx.y;
    const int lane = threadIdx.x & 31;
    const int q    = lane >> 3;
    const int cc   = lane & 7;
    const int qx = q & 1, qy = q >> 1;
    const int b = p >> 12, h = (p >> 6) & 63, w = p & 63;

    const float* offp = g_off  + (size_t)p * 144 + g * 18;
    const float* mp   = g_mask + (size_t)p * 72  + g * 9;
    const float* base = g_xpad + (size_t)b * HP * WP * CC + g * GCH + cc * 4;

    float mk[K2], mx = -1e30f;
#pragma unroll
    for (int k = 0; k < K2; k++) { mk[k] = mp[k]; mx = fmaxf(mx, mk[k]); }
    float den = 0.f;
#pragma unroll
    for (int k = 0; k < K2; k++) { mk[k] = __expf(mk[k] - mx); den += mk[k]; }
    float inv = 1.0f / den;

    float4 acc = make_float4(0.f, 0.f, 0.f, 0.f);
#pragma unroll
    for (int k = 0; k < K2; k++) {
        float px = (float)(PADB + w) + (float)(k % 3 - 1) + offp[k * 2 + 0];
        float py = (float)(PADB + h) + (float)(k / 3 - 1) + offp[k * 2 + 1];
        float x0f = floorf(px), y0f = floorf(py);
        int xq = (int)x0f + qx, yq = (int)y0f + qy;
        float wx = px - x0f, wy = py - y0f;
        float wq = (qx ? wx : 1.f - wx) * (qy ? wy : 1.f - wy) * (mk[k] * inv);

        if (xq >= 0 && xq < WP && yq >= 0 && yq < HP) {
            float4 v = *(const float4*)(base + ((size_t)yq * WP + xq) * CC);
            acc.x += v.x * wq; acc.y += v.y * wq;
            acc.z += v.z * wq; acc.w += v.w * wq;
        }
    }
#pragma unroll
    for (int off = 8; off <= 16; off <<= 1) {
        acc.x += __shfl_xor_sync(0xFFFFFFFFu, acc.x, off);
        acc.y += __shfl_xor_sync(0xFFFFFFFFu, acc.y, off);
        acc.z += __shfl_xor_sync(0xFFFFFFFFu, acc.z, off);
        acc.w += __shfl_xor_sync(0xFFFFFFFFu, acc.w, off);
    }
    if (lane < 8) {
        uint2 hi, lo;
        split4(acc, hi, lo);
        size_t ob = (size_t)p * CC + g * GCH + cc * 4;
        *(uint2*)&g_smh[ob] = hi;
        *(uint2*)&g_sml[ob] = lo;
    }
}

// ---------------------------------------------------------------------------
// Launch (kernel launches only; NO device symbols referenced from host code)
// ---------------------------------------------------------------------------
extern "C" void kernel_launch(void* const* d_in, const int* in_sizes, int n_in,
                              void* d_out, int out_size) {
    const float* inputs   = (const float*)d_in[0];
    const float* w_in     = (const float*)d_in[1];
    const float* b_in     = (const float*)d_in[2];
    const float* dw_k     = (const float*)d_in[3];
    const float* dw_b     = (const float*)d_in[4];
    const float* ln_gamma = (const float*)d_in[5];
    const float* ln_beta  = (const float*)d_in[6];
    const float* w_off    = (const float*)d_in[7];
    const float* b_off    = (const float*)d_in[8];
    const float* w_mask   = (const float*)d_in[9];
    const float* b_mask   = (const float*)d_in[10];
    const float* w_out    = (const float*)d_in[11];
    const float* b_out    = (const float*)d_in[12];
    float* out = (float*)d_out;

    {
        dim3 grid(256, 3);
        prep_weights<<<grid, 256>>>(w_in, w_off, w_mask, w_out, b_off, b_mask);
    }
    convert_inputs<<<(NPIX * CC / 4 + 255) / 256, 256>>>(inputs);
    zero_ring_kernel<<<(BATCH * 260 * 64 + 255) / 256, 256>>>();
    {
        dim3 grid(CC / 64, NPIX / 128);
        sgemm_bf16<0, 1, 0><<<grid, 256>>>(b_in, nullptr, CC);
    }
    dwlngelu_kernel<<<NPIX / 32, 256>>>(inputs, dw_k, dw_b, ln_gamma, ln_beta);
    {
        dim3 grid(256 / 64, NPIX / 128);
        sgemm_bf16<1, 2, 1><<<grid, 256>>>(nullptr, nullptr, 216);
    }
    {
        dim3 grid(NPIX / 8, GG);
        deform_sample_kernel<<<grid, 256>>>();
    }
    {
        dim3 grid(CC / 64, NPIX / 128);
        sgemm_bf16<2, 0, 2><<<grid, 256>>>(b_out, out, CC);
    }
    (void)in_sizes; (void)n_in; (void)out_size;
}

// round 15
// speedup vs baseline: 2.2711x; 1.0912x over previous
#include <cuda_runtime.h>
#include <cuda_bf16.h>
#include <cuda_fp16.h>
#include <math.h>
#include <stdint.h>

// ---------------------------------------------------------------------------
// Problem constants
// ---------------------------------------------------------------------------
#define BATCH 8
#define HH    64
#define WW    64
#define CC    256
#define GG    8
#define GCH   32
#define K2    9
#define PADB  1
#define HP    66
#define WP    66
#define NPIX  (BATCH*HH*WW) // 32768

// ---------------------------------------------------------------------------
// Scratch (device globals) — referenced ONLY from device code.
// ---------------------------------------------------------------------------
__device__ float g_xpad[BATCH * HP * WP * CC];       // padded x_proj (fp32)
__device__ float g_off [NPIX * 144];                 // offsets
__device__ float g_mask[NPIX * 72];                  // mask logits (softmax in sampler)

// bf16 hi/lo activation buffers (x_proj / out GEMM A operands)
__device__ __nv_bfloat16 g_inh [NPIX * CC], g_inl [NPIX * CC];
__device__ __nv_bfloat16 g_smh [NPIX * CC], g_sml [NPIX * CC];
// fp16 x1 (offset/mask GEMM A operand; single-MMA path)
__device__ __half g_x1f[NPIX * CC];

// Pre-split, pre-transposed weights
__device__ __nv_bfloat16 g_wTin_h [CC * CC], g_wTin_l [CC * CC];
__device__ __half        g_wTomf  [CC * CC];          // off|mask|zero, fp16
__device__ __nv_bfloat16 g_wTout_h[CC * CC], g_wTout_l[CC * CC];
__device__ float g_bom[CC];

// ---------------------------------------------------------------------------
// split helpers
// ---------------------------------------------------------------------------
__device__ __forceinline__ void split4(float4 v, uint2& hi, uint2& lo) {
    __nv_bfloat162 h01 = __floats2bfloat162_rn(v.x, v.y);
    __nv_bfloat162 h23 = __floats2bfloat162_rn(v.z, v.w);
    float2 f01 = __bfloat1622float2(h01);
    float2 f23 = __bfloat1622float2(h23);
    __nv_bfloat162 l01 = __floats2bfloat162_rn(v.x - f01.x, v.y - f01.y);
    __nv_bfloat162 l23 = __floats2bfloat162_rn(v.z - f23.x, v.w - f23.y);
    hi.x = reinterpret_cast<unsigned&>(h01); hi.y = reinterpret_cast<unsigned&>(h23);
    lo.x = reinterpret_cast<unsigned&>(l01); lo.y = reinterpret_cast<unsigned&>(l23);
}

__device__ __forceinline__ uint2 pack_f16x4(float4 v) {
    __half2 a = __floats2half2_rn(v.x, v.y);
    __half2 b = __floats2half2_rn(v.z, v.w);
    uint2 u;
    u.x = reinterpret_cast<unsigned&>(a);
    u.y = reinterpret_cast<unsigned&>(b);
    return u;
}

// ---------------------------------------------------------------------------
// Weight prep: transpose + convert. grid(256, 3), block 256 (tid = k).
// ---------------------------------------------------------------------------
__global__ void prep_weights(const float* __restrict__ w_in,
                             const float* __restrict__ w_off,
                             const float* __restrict__ w_mask,
                             const float* __restrict__ w_out,
                             const float* __restrict__ b_off,
                             const float* __restrict__ b_mask) {
    int n = blockIdx.x, mat = blockIdx.y, k = threadIdx.x;
    if (mat == 1) {
        float v;
        if (n < 144)      v = w_off [k * 144 + n];
        else if (n < 216) v = w_mask[k * 72 + (n - 144)];
        else              v = 0.f;
        g_wTomf[n * 256 + k] = __float2half(v);
        if (n == 0)
            g_bom[k] = (k < 144) ? b_off[k] : (k < 216 ? b_mask[k - 144] : 0.f);
        return;
    }
    float v;
    __nv_bfloat16 *dh, *dl;
    if (mat == 0) { v = w_in [k * 256 + n]; dh = g_wTin_h;  dl = g_wTin_l; }
    else          { v = w_out[k * 256 + n]; dh = g_wTout_h; dl = g_wTout_l; }
    __nv_bfloat16 h = __float2bfloat16_rn(v);
    __nv_bfloat16 l = __float2bfloat16_rn(v - __bfloat162float(h));
    dh[n * 256 + k] = h;
    dl[n * 256 + k] = l;
}

// ---------------------------------------------------------------------------
// Convert external inputs -> bf16 hi/lo  (thread = one float4)
// ---------------------------------------------------------------------------
__global__ void convert_inputs(const float* __restrict__ in) {
    int i = blockIdx.x * blockDim.x + threadIdx.x;
    if (i >= NPIX * CC / 4) return;
    float4 v = ((const float4*)in)[i];
    uint2 hi, lo;
    split4(v, hi, lo);
    ((uint2*)g_inh)[i] = hi;
    ((uint2*)g_inl)[i] = lo;
}

// ---------------------------------------------------------------------------
// Zero the 1-pixel ring of the padded buffer
// ---------------------------------------------------------------------------
__global__ void zero_ring_kernel() {
    int idx = blockIdx.x * blockDim.x + threadIdx.x;
    const int total = BATCH * 260 * 64;
    if (idx >= total) return;
    int p = idx >> 6, c4 = idx & 63;
    int b = p / 260, r = p % 260;
    int h, w;
    if (r < 66)       { h = 0;       w = r; }
    else if (r < 132) { h = 65;      w = r - 66; }
    else if (r < 196) { h = r - 131; w = 0; }
    else              { h = r - 195; w = 65; }
    size_t a = (((size_t)(b * HP + h) * WP + w) * CC) + c4 * 4;
    *(float4*)(g_xpad + a) = make_float4(0.f, 0.f, 0.f, 0.f);
}

// ---------------------------------------------------------------------------
// MMA / ldmatrix / cp.async helpers
// ---------------------------------------------------------------------------
#define MMA_BF16(d, a, b)                                                      \
    asm volatile("mma.sync.aligned.m16n8k16.row.col.f32.bf16.bf16.f32 "        \
        "{%0,%1,%2,%3}, {%4,%5,%6,%7}, {%8,%9}, {%0,%1,%2,%3};"                \
        : "+f"((d)[0]), "+f"((d)[1]), "+f"((d)[2]), "+f"((d)[3])               \
        : "r"((a)[0]), "r"((a)[1]), "r"((a)[2]), "r"((a)[3]),                  \
          "r"((b)[0]), "r"((b)[1]))

#define MMA_F16(d, a, b)                                                       \
    asm volatile("mma.sync.aligned.m16n8k16.row.col.f32.f16.f16.f32 "          \
        "{%0,%1,%2,%3}, {%4,%5,%6,%7}, {%8,%9}, {%0,%1,%2,%3};"                \
        : "+f"((d)[0]), "+f"((d)[1]), "+f"((d)[2]), "+f"((d)[3])               \
        : "r"((a)[0]), "r"((a)[1]), "r"((a)[2]), "r"((a)[3]),                  \
          "r"((b)[0]), "r"((b)[1]))

__device__ __forceinline__ void ldsm4(unsigned* r, uint32_t addr) {
    asm volatile("ldmatrix.sync.aligned.m8n8.x4.shared.b16 {%0,%1,%2,%3}, [%4];"
        : "=r"(r[0]), "=r"(r[1]), "=r"(r[2]), "=r"(r[3]) : "r"(addr));
}

__device__ __forceinline__ void cp16(uint32_t s, const void* g) {
    asm volatile("cp.async.cg.shared.global [%0], [%1], 16;" :: "r"(s), "l"(g));
}
__device__ __forceinline__ void cp_commit() {
    asm volatile("cp.async.commit_group;");
}
template<int N>
__device__ __forceinline__ void cp_wait() {
    asm volatile("cp.async.wait_group %0;" :: "n"(N));
}

// Swizzled smem offset for (row, chunk) with 32B rows, 2 chunks of 16B:
// physical slot = chunk ^ ((row>>2)&1). All addresses multiples of 16.
__device__ __forceinline__ uint32_t sw_off(int row, int chunk) {
    return (uint32_t)(row * 32 + ((chunk ^ ((row >> 2) & 1)) << 4));
}

// ---------------------------------------------------------------------------
// Tensor-core GEMM, cp.async 3-stage pipeline, one barrier per k-iter.
// C[M,N] = A[M,256] @ B[256,N] + bias
// BM=128, BN=64, BK=16, 256 threads (8 warps 4x2), warp tile 32x32.
// WSEL 0/2: bf16 hi/lo split, 3 MMAs per pair (x_proj / out).
// WSEL 1:   fp16 single-MMA path (off|mask), A=g_x1f, B=g_wTomf.
// SMEM: 32B rows, XOR-swizzled 16B chunks; 3 stages x 12288B = 36864B.
// SRC:  0 g_in, 2 g_sm (ignored for WSEL==1)
// DST:  0 ext, 1 g_xpad (padded layout), 2 fused off|mask split
// ---------------------------------------------------------------------------
#define BK     16
#define ST_AH  0
#define ST_AL  4096
#define ST_BH  8192
#define ST_BL  10240
#define ST_SZ  12288
#define NSTAGE 3

template<int SRC, int DST, int WSEL>
__global__ __launch_bounds__(256)
void sgemm_tc(const float* __restrict__ bias_ext,
              float* __restrict__ Cext,
              int N) {
    constexpr bool SPLIT = (WSEL != 1);
    const __nv_bfloat16* __restrict__ Agh = (SRC == 0) ? g_inh : g_smh;
    const __nv_bfloat16* __restrict__ Agl = (SRC == 0) ? g_inl : g_sml;
    const __nv_bfloat16* __restrict__ BTh = (WSEL == 0) ? g_wTin_h : g_wTout_h;
    const __nv_bfloat16* __restrict__ BTl = (WSEL == 0) ? g_wTin_l : g_wTout_l;
    const __half* __restrict__ Af16 = g_x1f;
    const __half* __restrict__ Bf16 = g_wTomf;
    const float* __restrict__ bias = (WSEL == 1) ? (const float*)g_bom : bias_ext;

    __shared__ __align__(128) char smem[NSTAGE * ST_SZ];
    const uint32_t s_base = (uint32_t)__cvta_generic_to_shared(smem);

    const int tid  = threadIdx.x;
    const int warp = tid >> 5;
    const int lane = tid & 31;
    const int wm = warp >> 1;   // 0..3 (32-row slice of 128)
    const int wn = warp & 1;    // 0..1 (32-col slice of 64)
    const int brow = blockIdx.y * 128;
    const int bcol = blockIdx.x * 64;

    float d[2][4][4];
#pragma unroll
    for (int i = 0; i < 2; i++)
#pragma unroll
        for (int j = 0; j < 4; j++)
#pragma unroll
            for (int k = 0; k < 4; k++) d[i][j][k] = 0.f;

    const int arow = tid >> 1;
    const int ac   = tid & 1;
    const int bhalf = tid >> 7;
    const int brw2  = (tid & 127) >> 1;
    const int bc    = tid & 1;

    auto ldgsts = [&](int kidx, int st) {
        int k0 = kidx * BK;
        uint32_t sb = s_base + st * ST_SZ;
        uint32_t dsA = sw_off(arow, ac);
        uint32_t dsB = sw_off(brw2, bc);
        if (SPLIT) {
            cp16(sb + ST_AH + dsA, Agh + (size_t)(brow + arow) * 256 + k0 + ac * 8);
            cp16(sb + ST_AL + dsA, Agl + (size_t)(brow + arow) * 256 + k0 + ac * 8);
            const __nv_bfloat16* bp =
                (bhalf ? BTl : BTh) + (size_t)(bcol + brw2) * 256 + k0 + bc * 8;
            cp16(sb + (bhalf ? ST_BL : ST_BH) + dsB, bp);
        } else {
            cp16(sb + ST_AH + dsA, Af16 + (size_t)(brow + arow) * 256 + k0 + ac * 8);
            if (bhalf == 0)
                cp16(sb + ST_BH + dsB, Bf16 + (size_t)(bcol + brw2) * 256 + k0 + bc * 8);
        }
    };

    const int t  = lane >> 3;
    const int lr = lane & 7;

    auto compute = [&](int st) {
        uint32_t sb = s_base + st * ST_SZ;
        unsigned ahf[2][4], alf[2][4], bhf[4][2], blf[4][2];
#pragma unroll
        for (int ms = 0; ms < 2; ms++) {
            int row = wm * 32 + ms * 16 + ((t & 1) << 3) + lr;
            uint32_t aoff = sw_off(row, t >> 1);
            ldsm4(ahf[ms], sb + ST_AH + aoff);
            if (SPLIT) ldsm4(alf[ms], sb + ST_AL + aoff);
        }
#pragma unroll
        for (int nb = 0; nb < 2; nb++) {
            int row = wn * 32 + nb * 16 + ((t >> 1) << 3) + lr;
            uint32_t boff = sw_off(row, t & 1);
            unsigned rh[4], rl[4];
            ldsm4(rh, sb + ST_BH + boff);
            bhf[nb * 2 + 0][0] = rh[0]; bhf[nb * 2 + 0][1] = rh[1];
            bhf[nb * 2 + 1][0] = rh[2]; bhf[nb * 2 + 1][1] = rh[3];
            if (SPLIT) {
                ldsm4(rl, sb + ST_BL + boff);
                blf[nb * 2 + 0][0] = rl[0]; blf[nb * 2 + 0][1] = rl[1];
                blf[nb * 2 + 1][0] = rl[2]; blf[nb * 2 + 1][1] = rl[3];
            }
        }
#pragma unroll
        for (int ms = 0; ms < 2; ms++)
#pragma unroll
            for (int ns = 0; ns < 4; ns++) {
                if (SPLIT) {
                    MMA_BF16(d[ms][ns], ahf[ms], bhf[ns]);
                    MMA_BF16(d[ms][ns], ahf[ms], blf[ns]);
                    MMA_BF16(d[ms][ns], alf[ms], bhf[ns]);
                } else {
                    MMA_F16(d[ms][ns], ahf[ms], bhf[ns]);
                }
            }
    };

    // pipeline: 16 k-iterations, 3 stages, one barrier per iteration
    ldgsts(0, 0); cp_commit();
    ldgsts(1, 1); cp_commit();
    int cs = 0, ws = 2;
    for (int it = 0; it < 16; it++) {
        if (it + 2 < 16) cp_wait<1>(); else cp_wait<0>();
        __syncthreads();
        if (it + 2 < 16) { ldgsts(it + 2, ws); cp_commit(); }
        compute(cs);
        ws = cs;
        cs = (cs == 2) ? 0 : cs + 1;
    }

    // epilogue
#pragma unroll
    for (int ms = 0; ms < 2; ms++) {
        int row0 = brow + wm * 32 + ms * 16 + (lane >> 2);
#pragma unroll
        for (int half = 0; half < 2; half++) {
            int row = row0 + half * 8;
#pragma unroll
            for (int ns = 0; ns < 4; ns++) {
                int col = bcol + wn * 32 + ns * 8 + 2 * (lane & 3);
                if (col >= N) continue;
                float2 v;
                v.x = d[ms][ns][half * 2 + 0] + bias[col];
                v.y = d[ms][ns][half * 2 + 1] + bias[col + 1];
                if (DST == 1) {
                    int b = row >> 12, h = (row >> 6) & 63, w = row & 63;
                    size_t ob = ((size_t)(b * HP + h + 1) * WP + (w + 1)) * CC;
                    *(float2*)&g_xpad[ob + col] = v;
                } else if (DST == 2) {
                    if (col < 144)      *(float2*)&g_off [(size_t)row * 144 + col] = v;
                    else                *(float2*)&g_mask[(size_t)row * 72 + col - 144] = v;
                } else {
                    *(float2*)&Cext[(size_t)row * N + col] = v;
                }
            }
        }
    }
}

// ---------------------------------------------------------------------------
// Depthwise 3x3 + LayerNorm + exact GELU. Warp = 4 consecutive pixels.
// Output: fp16 into g_x1f.
// ---------------------------------------------------------------------------
__global__ __launch_bounds__(256)
void dwlngelu_kernel(const float* __restrict__ in,
                     const float* __restrict__ dwk,
                     const float* __restrict__ dwb,
                     const float* __restrict__ gamma,
                     const float* __restrict__ beta) {
    const int warp = threadIdx.x >> 5;
    const int lane = threadIdx.x & 31;
    const int pb = blockIdx.x * 32 + warp * 4;
    const int b = pb >> 12, h = (pb >> 6) & 63, w0 = pb & 63;
    const int c0 = lane * 4, c1 = 128 + lane * 4;

    float4 bias0 = *(const float4*)(dwb + c0);
    float4 bias1 = *(const float4*)(dwb + c1);
    float4 a0[4], a1[4];
#pragma unroll
    for (int i = 0; i < 4; i++) { a0[i] = bias0; a1[i] = bias1; }

#pragma unroll
    for (int ky = 0; ky < 3; ky++) {
        int hh = h + ky - 1;
        if (hh < 0 || hh >= HH) continue;
        float4 kw0[3], kw1[3];
#pragma unroll
        for (int kx = 0; kx < 3; kx++) {
            kw0[kx] = *(const float4*)(dwk + (ky * 3 + kx) * CC + c0);
            kw1[kx] = *(const float4*)(dwk + (ky * 3 + kx) * CC + c1);
        }
        const float* row = in + (size_t)(b * HH + hh) * WW * CC;
#pragma unroll
        for (int j = 0; j < 6; j++) {
            int ww = w0 - 1 + j;
            if (ww < 0 || ww >= WW) continue;
            float4 x0 = *(const float4*)(row + (size_t)ww * CC + c0);
            float4 x1 = *(const float4*)(row + (size_t)ww * CC + c1);
#pragma unroll
            for (int i = 0; i < 4; i++) {
                int kx = j - i;
                if (kx < 0 || kx > 2) continue;
                a0[i].x += x0.x * kw0[kx].x; a0[i].y += x0.y * kw0[kx].y;
                a0[i].z += x0.z * kw0[kx].z; a0[i].w += x0.w * kw0[kx].w;
                a1[i].x += x1.x * kw1[kx].x; a1[i].y += x1.y * kw1[kx].y;
                a1[i].z += x1.z * kw1[kx].z; a1[i].w += x1.w * kw1[kx].w;
            }
        }
    }

    float4 ga0 = *(const float4*)(gamma + c0), ga1 = *(const float4*)(gamma + c1);
    float4 be0 = *(const float4*)(beta + c0),  be1 = *(const float4*)(beta + c1);

#pragma unroll
    for (int i = 0; i < 4; i++) {
        float4 s0 = a0[i], s1 = a1[i];
        float sum = s0.x + s0.y + s0.z + s0.w + s1.x + s1.y + s1.z + s1.w;
        float sq  = s0.x*s0.x + s0.y*s0.y + s0.z*s0.z + s0.w*s0.w
                  + s1.x*s1.x + s1.y*s1.y + s1.z*s1.z + s1.w*s1.w;
#pragma unroll
        for (int off = 16; off > 0; off >>= 1) {
            sum += __shfl_xor_sync(0xFFFFFFFFu, sum, off);
            sq  += __shfl_xor_sync(0xFFFFFFFFu, sq,  off);
        }
        float mu  = sum * (1.0f / 256.0f);
        float var = sq * (1.0f / 256.0f) - mu * mu;
        float rstd = rsqrtf(var + 1e-6f);

        float4 r0, r1;
        float y;
        y = (s0.x - mu) * rstd * ga0.x + be0.x; r0.x = 0.5f * y * (1.f + erff(y * 0.70710678118654752f));
        y = (s0.y - mu) * rstd * ga0.y + be0.y; r0.y = 0.5f * y * (1.f + erff(y * 0.70710678118654752f));
        y = (s0.z - mu) * rstd * ga0.z + be0.z; r0.z = 0.5f * y * (1.f + erff(y * 0.70710678118654752f));
        y = (s0.w - mu) * rstd * ga0.w + be0.w; r0.w = 0.5f * y * (1.f + erff(y * 0.70710678118654752f));
        y = (s1.x - mu) * rstd * ga1.x + be1.x; r1.x = 0.5f * y * (1.f + erff(y * 0.70710678118654752f));
        y = (s1.y - mu) * rstd * ga1.y + be1.y; r1.y = 0.5f * y * (1.f + erff(y * 0.70710678118654752f));
        y = (s1.z - mu) * rstd * ga1.z + be1.z; r1.z = 0.5f * y * (1.f + erff(y * 0.70710678118654752f));
        y = (s1.w - mu) * rstd * ga1.w + be1.w; r1.w = 0.5f * y * (1.f + erff(y * 0.70710678118654752f));

        size_t ob = (size_t)(pb + i) * CC;
        *(uint2*)&g_x1f[ob + c0] = pack_f16x4(r0);
        *(uint2*)&g_x1f[ob + c1] = pack_f16x4(r1);
    }
}

// ---------------------------------------------------------------------------
// Deformable bilinear gather + inline softmax.
// Warp = (pixel, group). lane = (corner q, channel chunk cc).
// ---------------------------------------------------------------------------
__global__ __launch_bounds__(256)
void deform_sample_kernel() {
    const int p    = blockIdx.x * 8 + (threadIdx.x >> 5);
    const int g    = blockIdx.y;
    const int lane = threadIdx.x & 31;
    const int q    = lane >> 3;
    const int cc   = lane & 7;
    const int qx = q & 1, qy = q >> 1;
    const int b = p >> 12, h = (p >> 6) & 63, w = p & 63;

    const float* offp = g_off  + (size_t)p * 144 + g * 18;
    const float* mp   = g_mask + (size_t)p * 72  + g * 9;
    const float* base = g_xpad + (size_t)b * HP * WP * CC + g * GCH + cc * 4;

    float mk[K2], mx = -1e30f;
#pragma unroll
    for (int k = 0; k < K2; k++) { mk[k] = mp[k]; mx = fmaxf(mx, mk[k]); }
    float den = 0.f;
#pragma unroll
    for (int k = 0; k < K2; k++) { mk[k] = __expf(mk[k] - mx); den += mk[k]; }
    float inv = 1.0f / den;

    float4 acc = make_float4(0.f, 0.f, 0.f, 0.f);
#pragma unroll
    for (int k = 0; k < K2; k++) {
        float px = (float)(PADB + w) + (float)(k % 3 - 1) + offp[k * 2 + 0];
        float py = (float)(PADB + h) + (float)(k / 3 - 1) + offp[k * 2 + 1];
        float x0f = floorf(px), y0f = floorf(py);
        int xq = (int)x0f + qx, yq = (int)y0f + qy;
        float wx = px - x0f, wy = py - y0f;
        float wq = (qx ? wx : 1.f - wx) * (qy ? wy : 1.f - wy) * (mk[k] * inv);

        if (xq >= 0 && xq < WP && yq >= 0 && yq < HP) {
            float4 v = *(const float4*)(base + ((size_t)yq * WP + xq) * CC);
            acc.x += v.x * wq; acc.y += v.y * wq;
            acc.z += v.z * wq; acc.w += v.w * wq;
        }
    }
#pragma unroll
    for (int off = 8; off <= 16; off <<= 1) {
        acc.x += __shfl_xor_sync(0xFFFFFFFFu, acc.x, off);
        acc.y += __shfl_xor_sync(0xFFFFFFFFu, acc.y, off);
        acc.z += __shfl_xor_sync(0xFFFFFFFFu, acc.z, off);
        acc.w += __shfl_xor_sync(0xFFFFFFFFu, acc.w, off);
    }
    if (lane < 8) {
        uint2 hi, lo;
        split4(acc, hi, lo);
        size_t ob = (size_t)p * CC + g * GCH + cc * 4;
        *(uint2*)&g_smh[ob] = hi;
        *(uint2*)&g_sml[ob] = lo;
    }
}

// ---------------------------------------------------------------------------
// Launch (kernel launches only; NO device symbols referenced from host code)
// ---------------------------------------------------------------------------
extern "C" void kernel_launch(void* const* d_in, const int* in_sizes, int n_in,
                              void* d_out, int out_size) {
    const float* inputs   = (const float*)d_in[0];
    const float* w_in     = (const float*)d_in[1];
    const float* b_in     = (const float*)d_in[2];
    const float* dw_k     = (const float*)d_in[3];
    const float* dw_b     = (const float*)d_in[4];
    const float* ln_gamma = (const float*)d_in[5];
    const float* ln_beta  = (const float*)d_in[6];
    const float* w_off    = (const float*)d_in[7];
    const float* b_off    = (const float*)d_in[8];
    const float* w_mask   = (const float*)d_in[9];
    const float* b_mask   = (const float*)d_in[10];
    const float* w_out    = (const float*)d_in[11];
    const float* b_out    = (const float*)d_in[12];
    float* out = (float*)d_out;

    {
        dim3 grid(256, 3);
        prep_weights<<<grid, 256>>>(w_in, w_off, w_mask, w_out, b_off, b_mask);
    }
    convert_inputs<<<(NPIX * CC / 4 + 255) / 256, 256>>>(inputs);
    zero_ring_kernel<<<(BATCH * 260 * 64 + 255) / 256, 256>>>();
    {
        dim3 grid(CC / 64, NPIX / 128);
        sgemm_tc<0, 1, 0><<<grid, 256>>>(b_in, nullptr, CC);
    }
    dwlngelu_kernel<<<NPIX / 32, 256>>>(inputs, dw_k, dw_b, ln_gamma, ln_beta);
    {
        dim3 grid(256 / 64, NPIX / 128);
        sgemm_tc<1, 2, 1><<<grid, 256>>>(nullptr, nullptr, 216);
    }
    {
        dim3 grid(NPIX / 8, GG);
        deform_sample_kernel<<<grid, 256>>>();
    }
    {
        dim3 grid(CC / 64, NPIX / 128);
        sgemm_tc<2, 0, 2><<<grid, 256>>>(b_out, out, CC);
    }
    (void)in_sizes; (void)n_in; (void)out_size;
}

// round 16
// speedup vs baseline: 2.5303x; 1.1141x over previous
#include <cuda_runtime.h>
#include <cuda_bf16.h>
#include <cuda_fp16.h>
#include <math.h>
#include <stdint.h>

// ---------------------------------------------------------------------------
// Problem constants
// ---------------------------------------------------------------------------
#define BATCH 8
#define HH    64
#define WW    64
#define CC    256
#define GG    8
#define GCH   32
#define K2    9
#define PADB  1
#define HP    66
#define WP    66
#define NPIX  (BATCH*HH*WW) // 32768

// ---------------------------------------------------------------------------
// Scratch (device globals) — referenced ONLY from device code.
// ---------------------------------------------------------------------------
__device__ float g_xpad[BATCH * HP * WP * CC];       // padded x_proj (fp32)
__device__ float g_off [NPIX * 144];                 // offsets
__device__ float g_mask[NPIX * 72];                  // mask logits (softmax in sampler)

// fp16 hi/lo activation buffers (x_proj / out GEMM A operands)
__device__ __half g_inh [NPIX * CC], g_inl [NPIX * CC];
__device__ __half g_smh [NPIX * CC], g_sml [NPIX * CC];
// fp16 x1 (offset/mask GEMM A operand; single-MMA path)
__device__ __half g_x1f[NPIX * CC];

// Pre-transposed fp16 weights [n][k]
__device__ __half g_wTinf [CC * CC];
__device__ __half g_wTomf [CC * CC];          // off|mask|zero
__device__ __half g_wToutf[CC * CC];
__device__ float g_bom[CC];

// ---------------------------------------------------------------------------
// fp16 split helpers
// ---------------------------------------------------------------------------
__device__ __forceinline__ void split4h(float4 v, uint2& hi, uint2& lo) {
    __half2 h01 = __floats2half2_rn(v.x, v.y);
    __half2 h23 = __floats2half2_rn(v.z, v.w);
    float2 f01 = __half22float2(h01);
    float2 f23 = __half22float2(h23);
    __half2 l01 = __floats2half2_rn(v.x - f01.x, v.y - f01.y);
    __half2 l23 = __floats2half2_rn(v.z - f23.x, v.w - f23.y);
    hi.x = reinterpret_cast<unsigned&>(h01); hi.y = reinterpret_cast<unsigned&>(h23);
    lo.x = reinterpret_cast<unsigned&>(l01); lo.y = reinterpret_cast<unsigned&>(l23);
}

__device__ __forceinline__ uint2 pack_f16x4(float4 v) {
    __half2 a = __floats2half2_rn(v.x, v.y);
    __half2 b = __floats2half2_rn(v.z, v.w);
    uint2 u;
    u.x = reinterpret_cast<unsigned&>(a);
    u.y = reinterpret_cast<unsigned&>(b);
    return u;
}

// ---------------------------------------------------------------------------
// Weight prep: transpose + fp16 convert. grid(256, 3), block 256 (tid = k).
// ---------------------------------------------------------------------------
__global__ void prep_weights(const float* __restrict__ w_in,
                             const float* __restrict__ w_off,
                             const float* __restrict__ w_mask,
                             const float* __restrict__ w_out,
                             const float* __restrict__ b_off,
                             const float* __restrict__ b_mask) {
    int n = blockIdx.x, mat = blockIdx.y, k = threadIdx.x;
    float v;
    __half* dst;
    if (mat == 0)      { v = w_in [k * 256 + n]; dst = g_wTinf; }
    else if (mat == 2) { v = w_out[k * 256 + n]; dst = g_wToutf; }
    else {
        if (n < 144)      v = w_off [k * 144 + n];
        else if (n < 216) v = w_mask[k * 72 + (n - 144)];
        else              v = 0.f;
        dst = g_wTomf;
        if (n == 0)
            g_bom[k] = (k < 144) ? b_off[k] : (k < 216 ? b_mask[k - 144] : 0.f);
    }
    dst[n * 256 + k] = __float2half(v);
}

// ---------------------------------------------------------------------------
// Convert external inputs -> fp16 hi/lo  (thread = one float4)
// ---------------------------------------------------------------------------
__global__ void convert_inputs(const float* __restrict__ in) {
    int i = blockIdx.x * blockDim.x + threadIdx.x;
    if (i >= NPIX * CC / 4) return;
    float4 v = ((const float4*)in)[i];
    uint2 hi, lo;
    split4h(v, hi, lo);
    ((uint2*)g_inh)[i] = hi;
    ((uint2*)g_inl)[i] = lo;
}

// ---------------------------------------------------------------------------
// Zero the 1-pixel ring of the padded buffer
// ---------------------------------------------------------------------------
__global__ void zero_ring_kernel() {
    int idx = blockIdx.x * blockDim.x + threadIdx.x;
    const int total = BATCH * 260 * 64;
    if (idx >= total) return;
    int p = idx >> 6, c4 = idx & 63;
    int b = p / 260, r = p % 260;
    int h, w;
    if (r < 66)       { h = 0;       w = r; }
    else if (r < 132) { h = 65;      w = r - 66; }
    else if (r < 196) { h = r - 131; w = 0; }
    else              { h = r - 195; w = 65; }
    size_t a = (((size_t)(b * HP + h) * WP + w) * CC) + c4 * 4;
    *(float4*)(g_xpad + a) = make_float4(0.f, 0.f, 0.f, 0.f);
}

// ---------------------------------------------------------------------------
// MMA / ldmatrix / cp.async helpers
// ---------------------------------------------------------------------------
#define MMA_F16(d, a, b)                                                       \
    asm volatile("mma.sync.aligned.m16n8k16.row.col.f32.f16.f16.f32 "          \
        "{%0,%1,%2,%3}, {%4,%5,%6,%7}, {%8,%9}, {%0,%1,%2,%3};"                \
        : "+f"((d)[0]), "+f"((d)[1]), "+f"((d)[2]), "+f"((d)[3])               \
        : "r"((a)[0]), "r"((a)[1]), "r"((a)[2]), "r"((a)[3]),                  \
          "r"((b)[0]), "r"((b)[1]))

__device__ __forceinline__ void ldsm4(unsigned* r, uint32_t addr) {
    asm volatile("ldmatrix.sync.aligned.m8n8.x4.shared.b16 {%0,%1,%2,%3}, [%4];"
        : "=r"(r[0]), "=r"(r[1]), "=r"(r[2]), "=r"(r[3]) : "r"(addr));
}

__device__ __forceinline__ void cp16(uint32_t s, const void* g) {
    asm volatile("cp.async.cg.shared.global [%0], [%1], 16;" :: "r"(s), "l"(g));
}
__device__ __forceinline__ void cp_commit() {
    asm volatile("cp.async.commit_group;");
}
template<int N>
__device__ __forceinline__ void cp_wait() {
    asm volatile("cp.async.wait_group %0;" :: "n"(N));
}

// Swizzled smem offset for (row, chunk) with 32B rows, 2 chunks of 16B:
// physical slot = chunk ^ ((row>>2)&1). All addresses multiples of 16.
__device__ __forceinline__ uint32_t sw_off(int row, int chunk) {
    return (uint32_t)(row * 32 + ((chunk ^ ((row >> 2) & 1)) << 4));
}

// ---------------------------------------------------------------------------
// fp16 tensor-core GEMM, cp.async 3-stage pipeline, one barrier per k-iter.
// C[M,N] = A[M,256] @ B[256,N] + bias
// BM=128, BN=64, BK=16, 256 threads (8 warps 4x2), warp tile 32x32.
// WSEL 0/2: A = fp16 hi/lo split, B single fp16 -> 2 MMAs per pair.
// WSEL 1:   A single fp16 (g_x1f), B single fp16 -> 1 MMA per pair.
// SMEM: 32B rows, XOR-swizzled 16B chunks; 3 stages x 12288B = 36864B.
// SRC:  0 g_in, 2 g_sm (ignored for WSEL==1)
// DST:  0 ext, 1 g_xpad (padded layout), 2 fused off|mask split
// ---------------------------------------------------------------------------
#define BK     16
#define ST_AH  0
#define ST_AL  4096
#define ST_BH  8192
#define ST_SZ  12288
#define NSTAGE 3

template<int SRC, int DST, int WSEL>
__global__ __launch_bounds__(256)
void sgemm_tc(const float* __restrict__ bias_ext,
              float* __restrict__ Cext,
              int N) {
    constexpr bool SPLIT = (WSEL != 1);
    const __half* __restrict__ Ah16 =
        (WSEL == 1) ? g_x1f : (SRC == 0) ? g_inh : g_smh;
    const __half* __restrict__ Al16 = (SRC == 0) ? g_inl : g_sml;
    const __half* __restrict__ B16 =
        (WSEL == 0) ? g_wTinf : (WSEL == 1) ? g_wTomf : g_wToutf;
    const float* __restrict__ bias = (WSEL == 1) ? (const float*)g_bom : bias_ext;

    __shared__ __align__(128) char smem[NSTAGE * ST_SZ];
    const uint32_t s_base = (uint32_t)__cvta_generic_to_shared(smem);

    const int tid  = threadIdx.x;
    const int warp = tid >> 5;
    const int lane = tid & 31;
    const int wm = warp >> 1;   // 0..3 (32-row slice of 128)
    const int wn = warp & 1;    // 0..1 (32-col slice of 64)
    const int brow = blockIdx.y * 128;
    const int bcol = blockIdx.x * 64;

    float d[2][4][4];
#pragma unroll
    for (int i = 0; i < 2; i++)
#pragma unroll
        for (int j = 0; j < 4; j++)
#pragma unroll
            for (int k = 0; k < 4; k++) d[i][j][k] = 0.f;

    const int arow = tid >> 1;
    const int ac   = tid & 1;
    const int bhalf = tid >> 7;
    const int brw2  = (tid & 127) >> 1;
    const int bc    = tid & 1;

    auto ldgsts = [&](int kidx, int st) {
        int k0 = kidx * BK;
        uint32_t sb = s_base + st * ST_SZ;
        uint32_t dsA = sw_off(arow, ac);
        cp16(sb + ST_AH + dsA, Ah16 + (size_t)(brow + arow) * 256 + k0 + ac * 8);
        if (SPLIT)
            cp16(sb + ST_AL + dsA, Al16 + (size_t)(brow + arow) * 256 + k0 + ac * 8);
        if (bhalf == 0) {
            uint32_t dsB = sw_off(brw2, bc);
            cp16(sb + ST_BH + dsB, B16 + (size_t)(bcol + brw2) * 256 + k0 + bc * 8);
        }
    };

    const int t  = lane >> 3;
    const int lr = lane & 7;

    auto compute = [&](int st) {
        uint32_t sb = s_base + st * ST_SZ;
        unsigned ahf[2][4], alf[2][4], bhf[4][2];
#pragma unroll
        for (int ms = 0; ms < 2; ms++) {
            int row = wm * 32 + ms * 16 + ((t & 1) << 3) + lr;
            uint32_t aoff = sw_off(row, t >> 1);
            ldsm4(ahf[ms], sb + ST_AH + aoff);
            if (SPLIT) ldsm4(alf[ms], sb + ST_AL + aoff);
        }
#pragma unroll
        for (int nb = 0; nb < 2; nb++) {
            int row = wn * 32 + nb * 16 + ((t >> 1) << 3) + lr;
            uint32_t boff = sw_off(row, t & 1);
            unsigned rh[4];
            ldsm4(rh, sb + ST_BH + boff);
            bhf[nb * 2 + 0][0] = rh[0]; bhf[nb * 2 + 0][1] = rh[1];
            bhf[nb * 2 + 1][0] = rh[2]; bhf[nb * 2 + 1][1] = rh[3];
        }
#pragma unroll
        for (int ms = 0; ms < 2; ms++)
#pragma unroll
            for (int ns = 0; ns < 4; ns++) {
                MMA_F16(d[ms][ns], ahf[ms], bhf[ns]);
                if (SPLIT) MMA_F16(d[ms][ns], alf[ms], bhf[ns]);
            }
    };

    // pipeline: 16 k-iterations, 3 stages, one barrier per iteration
    ldgsts(0, 0); cp_commit();
    ldgsts(1, 1); cp_commit();
    int cs = 0, ws = 2;
    for (int it = 0; it < 16; it++) {
        if (it + 2 < 16) cp_wait<1>(); else cp_wait<0>();
        __syncthreads();
        if (it + 2 < 16) { ldgsts(it + 2, ws); cp_commit(); }
        compute(cs);
        ws = cs;
        cs = (cs == 2) ? 0 : cs + 1;
    }

    // epilogue
#pragma unroll
    for (int ms = 0; ms < 2; ms++) {
        int row0 = brow + wm * 32 + ms * 16 + (lane >> 2);
#pragma unroll
        for (int half = 0; half < 2; half++) {
            int row = row0 + half * 8;
#pragma unroll
            for (int ns = 0; ns < 4; ns++) {
                int col = bcol + wn * 32 + ns * 8 + 2 * (lane & 3);
                if (col >= N) continue;
                float2 v;
                v.x = d[ms][ns][half * 2 + 0] + bias[col];
                v.y = d[ms][ns][half * 2 + 1] + bias[col + 1];
                if (DST == 1) {
                    int b = row >> 12, h = (row >> 6) & 63, w = row & 63;
                    size_t ob = ((size_t)(b * HP + h + 1) * WP + (w + 1)) * CC;
                    *(float2*)&g_xpad[ob + col] = v;
                } else if (DST == 2) {
                    if (col < 144)      *(float2*)&g_off [(size_t)row * 144 + col] = v;
                    else                *(float2*)&g_mask[(size_t)row * 72 + col - 144] = v;
                } else {
                    *(float2*)&Cext[(size_t)row * N + col] = v;
                }
            }
        }
    }
}

// ---------------------------------------------------------------------------
// Depthwise 3x3 + LayerNorm + exact GELU. Warp = 4 consecutive pixels.
// Output: fp16 into g_x1f.
// ---------------------------------------------------------------------------
__global__ __launch_bounds__(256)
void dwlngelu_kernel(const float* __restrict__ in,
                     const float* __restrict__ dwk,
                     const float* __restrict__ dwb,
                     const float* __restrict__ gamma,
                     const float* __restrict__ beta) {
    const int warp = threadIdx.x >> 5;
    const int lane = threadIdx.x & 31;
    const int pb = blockIdx.x * 32 + warp * 4;
    const int b = pb >> 12, h = (pb >> 6) & 63, w0 = pb & 63;
    const int c0 = lane * 4, c1 = 128 + lane * 4;

    float4 bias0 = *(const float4*)(dwb + c0);
    float4 bias1 = *(const float4*)(dwb + c1);
    float4 a0[4], a1[4];
#pragma unroll
    for (int i = 0; i < 4; i++) { a0[i] = bias0; a1[i] = bias1; }

#pragma unroll
    for (int ky = 0; ky < 3; ky++) {
        int hh = h + ky - 1;
        if (hh < 0 || hh >= HH) continue;
        float4 kw0[3], kw1[3];
#pragma unroll
        for (int kx = 0; kx < 3; kx++) {
            kw0[kx] = *(const float4*)(dwk + (ky * 3 + kx) * CC + c0);
            kw1[kx] = *(const float4*)(dwk + (ky * 3 + kx) * CC + c1);
        }
        const float* row = in + (size_t)(b * HH + hh) * WW * CC;
#pragma unroll
        for (int j = 0; j < 6; j++) {
            int ww = w0 - 1 + j;
            if (ww < 0 || ww >= WW) continue;
            float4 x0 = *(const float4*)(row + (size_t)ww * CC + c0);
            float4 x1 = *(const float4*)(row + (size_t)ww * CC + c1);
#pragma unroll
            for (int i = 0; i < 4; i++) {
                int kx = j - i;
                if (kx < 0 || kx > 2) continue;
                a0[i].x += x0.x * kw0[kx].x; a0[i].y += x0.y * kw0[kx].y;
                a0[i].z += x0.z * kw0[kx].z; a0[i].w += x0.w * kw0[kx].w;
                a1[i].x += x1.x * kw1[kx].x; a1[i].y += x1.y * kw1[kx].y;
                a1[i].z += x1.z * kw1[kx].z; a1[i].w += x1.w * kw1[kx].w;
            }
        }
    }

    float4 ga0 = *(const float4*)(gamma + c0), ga1 = *(const float4*)(gamma + c1);
    float4 be0 = *(const float4*)(beta + c0),  be1 = *(const float4*)(beta + c1);

#pragma unroll
    for (int i = 0; i < 4; i++) {
        float4 s0 = a0[i], s1 = a1[i];
        float sum = s0.x + s0.y + s0.z + s0.w + s1.x + s1.y + s1.z + s1.w;
        float sq  = s0.x*s0.x + s0.y*s0.y + s0.z*s0.z + s0.w*s0.w
                  + s1.x*s1.x + s1.y*s1.y + s1.z*s1.z + s1.w*s1.w;
#pragma unroll
        for (int off = 16; off > 0; off >>= 1) {
            sum += __shfl_xor_sync(0xFFFFFFFFu, sum, off);
            sq  += __shfl_xor_sync(0xFFFFFFFFu, sq,  off);
        }
        float mu  = sum * (1.0f / 256.0f);
        float var = sq * (1.0f / 256.0f) - mu * mu;
        float rstd = rsqrtf(var + 1e-6f);

        float4 r0, r1;
        float y;
        y = (s0.x - mu) * rstd * ga0.x + be0.x; r0.x = 0.5f * y * (1.f + erff(y * 0.70710678118654752f));
        y = (s0.y - mu) * rstd * ga0.y + be0.y; r0.y = 0.5f * y * (1.f + erff(y * 0.70710678118654752f));
        y = (s0.z - mu) * rstd * ga0.z + be0.z; r0.z = 0.5f * y * (1.f + erff(y * 0.70710678118654752f));
        y = (s0.w - mu) * rstd * ga0.w + be0.w; r0.w = 0.5f * y * (1.f + erff(y * 0.70710678118654752f));
        y = (s1.x - mu) * rstd * ga1.x + be1.x; r1.x = 0.5f * y * (1.f + erff(y * 0.70710678118654752f));
        y = (s1.y - mu) * rstd * ga1.y + be1.y; r1.y = 0.5f * y * (1.f + erff(y * 0.70710678118654752f));
        y = (s1.z - mu) * rstd * ga1.z + be1.z; r1.z = 0.5f * y * (1.f + erff(y * 0.70710678118654752f));
        y = (s1.w - mu) * rstd * ga1.w + be1.w; r1.w = 0.5f * y * (1.f + erff(y * 0.70710678118654752f));

        size_t ob = (size_t)(pb + i) * CC;
        *(uint2*)&g_x1f[ob + c0] = pack_f16x4(r0);
        *(uint2*)&g_x1f[ob + c1] = pack_f16x4(r1);
    }
}

// ---------------------------------------------------------------------------
// Deformable bilinear gather + inline softmax.
// Warp = (pixel, group). lane = (corner q, channel chunk cc).
// Output fp16 hi/lo into g_smh / g_sml.
// ---------------------------------------------------------------------------
__global__ __launch_bounds__(256)
void deform_sample_kernel() {
    const int p    = blockIdx.x * 8 + (threadIdx.x >> 5);
    const int g    = blockIdx.y;
    const int lane = threadIdx.x & 31;
    const int q    = lane >> 3;
    const int cc   = lane & 7;
    const int qx = q & 1, qy = q >> 1;
    const int b = p >> 12, h = (p >> 6) & 63, w = p & 63;

    const float* offp = g_off  + (size_t)p * 144 + g * 18;
    const float* mp   = g_mask + (size_t)p * 72  + g * 9;
    const float* base = g_xpad + (size_t)b * HP * WP * CC + g * GCH + cc * 4;

    float mk[K2], mx = -1e30f;
#pragma unroll
    for (int k = 0; k < K2; k++) { mk[k] = mp[k]; mx = fmaxf(mx, mk[k]); }
    float den = 0.f;
#pragma unroll
    for (int k = 0; k < K2; k++) { mk[k] = __expf(mk[k] - mx); den += mk[k]; }
    float inv = 1.0f / den;

    float4 acc = make_float4(0.f, 0.f, 0.f, 0.f);
#pragma unroll
    for (int k = 0; k < K2; k++) {
        float px = (float)(PADB + w) + (float)(k % 3 - 1) + offp[k * 2 + 0];
        float py = (float)(PADB + h) + (float)(k / 3 - 1) + offp[k * 2 + 1];
        float x0f = floorf(px), y0f = floorf(py);
        int xq = (int)x0f + qx, yq = (int)y0f + qy;
        float wx = px - x0f, wy = py - y0f;
        float wq = (qx ? wx : 1.f - wx) * (qy ? wy : 1.f - wy) * (mk[k] * inv);

        if (xq >= 0 && xq < WP && yq >= 0 && yq < HP) {
            float4 v = *(const float4*)(base + ((size_t)yq * WP + xq) * CC);
            acc.x += v.x * wq; acc.y += v.y * wq;
            acc.z += v.z * wq; acc.w += v.w * wq;
        }
    }
#pragma unroll
    for (int off = 8; off <= 16; off <<= 1) {
        acc.x += __shfl_xor_sync(0xFFFFFFFFu, acc.x, off);
        acc.y += __shfl_xor_sync(0xFFFFFFFFu, acc.y, off);
        acc.z += __shfl_xor_sync(0xFFFFFFFFu, acc.z, off);
        acc.w += __shfl_xor_sync(0xFFFFFFFFu, acc.w, off);
    }
    if (lane < 8) {
        uint2 hi, lo;
        split4h(acc, hi, lo);
        size_t ob = (size_t)p * CC + g * GCH + cc * 4;
        *(uint2*)&g_smh[ob] = hi;
        *(uint2*)&g_sml[ob] = lo;
    }
}

// ---------------------------------------------------------------------------
// Launch (kernel launches only; NO device symbols referenced from host code)
// ---------------------------------------------------------------------------
extern "C" void kernel_launch(void* const* d_in, const int* in_sizes, int n_in,
                              void* d_out, int out_size) {
    const float* inputs   = (const float*)d_in[0];
    const float* w_in     = (const float*)d_in[1];
    const float* b_in     = (const float*)d_in[2];
    const float* dw_k     = (const float*)d_in[3];
    const float* dw_b     = (const float*)d_in[4];
    const float* ln_gamma = (const float*)d_in[5];
    const float* ln_beta  = (const float*)d_in[6];
    const float* w_off    = (const float*)d_in[7];
    const float* b_off    = (const float*)d_in[8];
    const float* w_mask   = (const float*)d_in[9];
    const float* b_mask   = (const float*)d_in[10];
    const float* w_out    = (const float*)d_in[11];
    const float* b_out    = (const float*)d_in[12];
    float* out = (float*)d_out;

    {
        dim3 grid(256, 3);
        prep_weights<<<grid, 256>>>(w_in, w_off, w_mask, w_out, b_off, b_mask);
    }
    convert_inputs<<<(NPIX * CC / 4 + 255) / 256, 256>>>(inputs);
    zero_ring_kernel<<<(BATCH * 260 * 64 + 255) / 256, 256>>>();
    {
        dim3 grid(CC / 64, NPIX / 128);
        sgemm_tc<0, 1, 0><<<grid, 256>>>(b_in, nullptr, CC);
    }
    dwlngelu_kernel<<<NPIX / 32, 256>>>(inputs, dw_k, dw_b, ln_gamma, ln_beta);
    {
        dim3 grid(256 / 64, NPIX / 128);
        sgemm_tc<1, 2, 1><<<grid, 256>>>(nullptr, nullptr, 216);
    }
    {
        dim3 grid(NPIX / 8, GG);
        deform_sample_kernel<<<grid, 256>>>();
    }
    {
        dim3 grid(CC / 64, NPIX / 128);
        sgemm_tc<2, 0, 2><<<grid, 256>>>(b_out, out, CC);
    }
    (void)in_sizes; (void)n_in; (void)out_size;
}